// round 1
// baseline (speedup 1.0000x reference)
#include <cuda_runtime.h>
#include <cuda_bf16.h>
#include <math.h>

#define NATOMS 32768
#define MNBR   12
#define ORIG   92
#define NBRF   41
#define AF     64
#define TWOAF  128
#define KTOT   (2*AF + NBRF)   // 169
#define EDGES  (NATOMS*MNBR)   // 393216
#define NCONV  3
#define ATOMS_PER 32
#define NCRYS  (NATOMS/ATOMS_PER)  // 1024
#define HF     128
#define BNEPS  1e-5f

// ---------------- scratch (device globals: allocation-free) ----------------
__device__ float d_x[NATOMS*AF];                 // atom features (8.4 MB)
__device__ float d_g[(size_t)EDGES*TWOAF];       // edge pre-activations (201 MB)
__device__ float d_summed[NATOMS*AF];
__device__ float d_s1[TWOAF], d_q1[TWOAF];       // BN1 accum
__device__ float d_scale1[TWOAF], d_shift1[TWOAF];
__device__ float d_s2[AF], d_q2[AF];             // BN2 accum
__device__ float d_scale2[AF], d_shift2[AF];

__device__ __forceinline__ float softplusf(float x) {
    return fmaxf(x, 0.0f) + log1pf(expf(-fabsf(x)));
}
__device__ __forceinline__ float sigmoidf(float x) {
    return 1.0f / (1.0f + expf(-x));
}

// ---------------- embedding: x = atom_fea @ emb_W + emb_b ----------------
__global__ __launch_bounds__(256) void k_embed(
    const float* __restrict__ atom_fea,
    const float* __restrict__ W,   // (92,64)
    const float* __restrict__ b)
{
    __shared__ float W_sh[ORIG*AF];     // 23.5 KB
    __shared__ float a_sh[4][ORIG];
    int tid = threadIdx.x;
    for (int i = tid; i < ORIG*AF; i += 256) W_sh[i] = W[i];
    int r0 = blockIdx.x * 4;
    for (int i = tid; i < 4*ORIG; i += 256) {
        int r = i / ORIG, k = i % ORIG;
        a_sh[r][k] = atom_fea[(r0 + r)*ORIG + k];
    }
    __syncthreads();
    int rl = tid >> 6;          // 0..3
    int c  = tid & 63;          // 0..63
    float acc = b[c];
    #pragma unroll 4
    for (int k = 0; k < ORIG; k++) acc += a_sh[rl][k] * W_sh[k*AF + c];
    d_x[(r0 + rl)*AF + c] = acc;
}

// ---------------- zero BN accumulators ----------------
__global__ void k_zero_stats() {
    int t = threadIdx.x;
    if (t < TWOAF) { d_s1[t] = 0.f; d_q1[t] = 0.f; }
    if (t < AF)    { d_s2[t] = 0.f; d_q2[t] = 0.f; }
}

// ---------------- edge GEMM: g = [x_i, x_nbr, nbr_fea] @ W + b ----------------
// block = 32 edges x 128 cols; 256 threads: (el = tid>>3, cg = tid&7)
// thread computes cols { q*32 + cg*4 + j : q<4, j<4 }  (conflict-free LDS.128 on W)
__global__ __launch_bounds__(256) void k_edge_gemm(
    const float* __restrict__ nbr_fea,   // (N,M,41) flat
    const int*   __restrict__ nbr_idx,   // (N,M) flat
    const float* __restrict__ Wc,        // (169,128)
    const float* __restrict__ bc)        // (128)
{
    extern __shared__ float sh[];
    float* W_sh   = sh;                   // 169*128
    float* tot_sh = sh + KTOT*TWOAF;      // 32*169
    __shared__ int nb_sh[32];

    int tid = threadIdx.x;
    int e0  = blockIdx.x * 32;

    // stage W (vectorized)
    {
        const float4* Wv = (const float4*)Wc;
        float4* Wsv = (float4*)W_sh;
        for (int i = tid; i < KTOT*TWOAF/4; i += 256) Wsv[i] = Wv[i];
    }
    if (tid < 32) nb_sh[tid] = nbr_idx[e0 + tid];
    __syncthreads();

    // stage tot tile: [el][k]  k<64: self, k<128: neighbor, else nbr_fea
    for (int i = tid; i < 32*KTOT; i += 256) {
        int el = i / KTOT, k = i % KTOT;
        int e  = e0 + el;
        int a  = e / MNBR;
        float v;
        if (k < AF)             v = d_x[a*AF + k];
        else if (k < 2*AF)      v = d_x[nb_sh[el]*AF + (k - AF)];
        else                    v = nbr_fea[(size_t)e*NBRF + (k - 2*AF)];
        tot_sh[el*KTOT + k] = v;
    }
    __syncthreads();

    int el = tid >> 3;
    int cg = tid & 7;
    float acc[4][4];
    #pragma unroll
    for (int q = 0; q < 4; q++) {
        #pragma unroll
        for (int j = 0; j < 4; j++) acc[q][j] = bc[q*32 + cg*4 + j];
    }

    const float* trow = &tot_sh[el*KTOT];
    for (int k = 0; k < KTOT; k++) {
        float v = trow[k];
        const float* wr = &W_sh[k*TWOAF + cg*4];
        #pragma unroll
        for (int q = 0; q < 4; q++) {
            float4 w = *(const float4*)(wr + q*32);
            acc[q][0] += v * w.x;
            acc[q][1] += v * w.y;
            acc[q][2] += v * w.z;
            acc[q][3] += v * w.w;
        }
    }

    float* gout = &d_g[(size_t)(e0 + el)*TWOAF + cg*4];
    #pragma unroll
    for (int q = 0; q < 4; q++) {
        *(float4*)(gout + q*32) = make_float4(acc[q][0], acc[q][1], acc[q][2], acc[q][3]);
    }
}

// ---------------- BN1 stats over (E,128) ----------------
__global__ __launch_bounds__(128) void k_stats1() {
    int c = threadIdx.x;
    float s = 0.f, q = 0.f;
    for (int r = blockIdx.x; r < EDGES; r += gridDim.x) {
        float v = d_g[(size_t)r*TWOAF + c];
        s += v; q += v*v;
    }
    atomicAdd(&d_s1[c], s);
    atomicAdd(&d_q1[c], q);
}

__global__ void k_fin1(const float* __restrict__ g1, const float* __restrict__ b1) {
    int c = threadIdx.x;   // 128
    float inv_n = 1.0f / (float)EDGES;
    float mu  = d_s1[c] * inv_n;
    float var = d_q1[c] * inv_n - mu*mu;
    float sc  = rsqrtf(var + BNEPS) * g1[c];
    d_scale1[c] = sc;
    d_shift1[c] = b1[c] - mu * sc;
}

// ---------------- gate + sum over neighbors, BN2 stats ----------------
// block = 4 atoms x 64 cols
__global__ __launch_bounds__(256) void k_gate_sum() {
    __shared__ float s2_sh[AF], q2_sh[AF];
    int tid = threadIdx.x;
    if (tid < AF) { s2_sh[tid] = 0.f; q2_sh[tid] = 0.f; }
    __syncthreads();

    int al = tid >> 6, c = tid & 63;
    int a  = blockIdx.x*4 + al;
    float sc_f = d_scale1[c],      sh_f = d_shift1[c];
    float sc_s = d_scale1[c + AF], sh_s = d_shift1[c + AF];

    float acc = 0.f;
    size_t base = (size_t)a * MNBR * TWOAF;
    #pragma unroll
    for (int m = 0; m < MNBR; m++) {
        float f = d_g[base + m*TWOAF + c]      * sc_f + sh_f;
        float s = d_g[base + m*TWOAF + c + AF] * sc_s + sh_s;
        acc += sigmoidf(f) * softplusf(s);
    }
    d_summed[a*AF + c] = acc;
    atomicAdd(&s2_sh[c], acc);
    atomicAdd(&q2_sh[c], acc*acc);
    __syncthreads();
    if (tid < AF) {
        atomicAdd(&d_s2[tid], s2_sh[tid]);
        atomicAdd(&d_q2[tid], q2_sh[tid]);
    }
}

__global__ void k_fin2(const float* __restrict__ g2, const float* __restrict__ b2) {
    int c = threadIdx.x;  // 64
    float inv_n = 1.0f / (float)NATOMS;
    float mu  = d_s2[c] * inv_n;
    float var = d_q2[c] * inv_n - mu*mu;
    float sc  = rsqrtf(var + BNEPS) * g2[c];
    d_scale2[c] = sc;
    d_shift2[c] = b2[c] - mu * sc;
}

// ---------------- residual update: x = softplus(x + BN2(summed)) ----------------
__global__ __launch_bounds__(256) void k_update_x() {
    int i = blockIdx.x*256 + threadIdx.x;
    int c = i & (AF-1);
    float v = d_summed[i] * d_scale2[c] + d_shift2[c];
    float t = d_x[i] + v;
    d_x[i] = softplusf(t);
}

// ---------------- pool + head MLP ----------------
__global__ __launch_bounds__(128) void k_head(
    const float* __restrict__ fc1W, const float* __restrict__ fc1b,
    const float* __restrict__ fc2W, const float* __restrict__ fc2b,
    const float* __restrict__ outW, const float* __restrict__ outb,
    float* __restrict__ out)
{
    __shared__ float p[AF];
    __shared__ float h1[HF];
    __shared__ float red[HF];
    int tid = threadIdx.x;
    int b = blockIdx.x;

    if (tid < AF) {
        const float* xb = &d_x[(size_t)b * ATOMS_PER * AF];
        float s = 0.f;
        #pragma unroll
        for (int a = 0; a < ATOMS_PER; a++) s += xb[a*AF + tid];
        p[tid] = softplusf(s * (1.0f/ATOMS_PER));
    }
    __syncthreads();

    float acc = fc1b[tid];
    #pragma unroll 4
    for (int k = 0; k < AF; k++) acc += p[k] * fc1W[k*HF + tid];
    h1[tid] = softplusf(acc);
    __syncthreads();

    float acc2 = fc2b[tid];
    #pragma unroll 4
    for (int k = 0; k < HF; k++) acc2 += h1[k] * fc2W[k*HF + tid];
    float h2 = softplusf(acc2);

    red[tid] = h2 * outW[tid];
    __syncthreads();
    for (int s = HF/2; s > 0; s >>= 1) {
        if (tid < s) red[tid] += red[tid + s];
        __syncthreads();
    }
    if (tid == 0) out[b] = red[0] + outb[0];
}

// ---------------- launch ----------------
extern "C" void kernel_launch(void* const* d_in, const int* in_sizes, int n_in,
                              void* d_out, int out_size)
{
    const float* atom_fea = (const float*)d_in[0];
    const float* nbr_fea  = (const float*)d_in[1];
    const int*   nbr_idx  = (const int*)  d_in[2];
    // d_in[3] = crystal_id (contiguous arange/32 by construction; contiguity used)
    const float* embW  = (const float*)d_in[4];
    const float* embB  = (const float*)d_in[5];
    const float* convW = (const float*)d_in[6];
    const float* convB = (const float*)d_in[7];
    const float* bn1g  = (const float*)d_in[8];
    const float* bn1b  = (const float*)d_in[9];
    const float* bn2g  = (const float*)d_in[10];
    const float* bn2b  = (const float*)d_in[11];
    const float* fc1W  = (const float*)d_in[12];
    const float* fc1b  = (const float*)d_in[13];
    const float* fc2W  = (const float*)d_in[14];
    const float* fc2b  = (const float*)d_in[15];
    const float* outW  = (const float*)d_in[16];
    const float* outb  = (const float*)d_in[17];
    float* out = (float*)d_out;

    const int smem_gemm = (KTOT*TWOAF + 32*KTOT) * (int)sizeof(float);  // 108160 B
    cudaFuncSetAttribute(k_edge_gemm, cudaFuncAttributeMaxDynamicSharedMemorySize, smem_gemm);

    k_embed<<<NATOMS/4, 256>>>(atom_fea, embW, embB);

    for (int l = 0; l < NCONV; l++) {
        k_zero_stats<<<1, 256>>>();
        k_edge_gemm<<<EDGES/32, 256, smem_gemm>>>(nbr_fea, nbr_idx,
                                                  convW + (size_t)l*KTOT*TWOAF,
                                                  convB + l*TWOAF);
        k_stats1<<<1024, 128>>>();
        k_fin1<<<1, 128>>>(bn1g + l*TWOAF, bn1b + l*TWOAF);
        k_gate_sum<<<NATOMS/4, 256>>>();
        k_fin2<<<1, 64>>>(bn2g + l*AF, bn2b + l*AF);
        k_update_x<<<NATOMS*AF/256, 256>>>();
    }

    k_head<<<NCRYS, 128>>>(fc1W, fc1b, fc2W, fc2b, outW, outb, out);
}

// round 4
// speedup vs baseline: 1.8021x; 1.8021x over previous
#include <cuda_runtime.h>
#include <cuda_bf16.h>
#include <math.h>

#define NATOMS 32768
#define MNBR   12
#define ORIG   92
#define NBRF   41
#define AF     64
#define TWOAF  128
#define KTOT   (2*AF + NBRF)   // 169
#define EDGES  (NATOMS*MNBR)   // 393216
#define NTILES (EDGES/32)      // 12288
#define NCONV  3
#define ATOMS_PER 32
#define NCRYS  (NATOMS/ATOMS_PER)  // 1024
#define HF     128
#define BNEPS  1e-5f

// ---------------- scratch (device globals: allocation-free) ----------------
__device__ float d_x[NATOMS*AF];                 // atom features
__device__ float d_g[(size_t)EDGES*TWOAF];       // edge pre-activations (201 MB)
__device__ float d_summed[NATOMS*AF];
__device__ float d_s1[TWOAF], d_q1[TWOAF];       // BN1 accum
__device__ float d_scale1[TWOAF], d_shift1[TWOAF];
__device__ float d_s2[AF], d_q2[AF];             // BN2 accum
__device__ float d_scale2[AF], d_shift2[AF];

// fast-math activations (MUFU-based, ~1e-7 abs err: fine vs 1e-3 tolerance)
__device__ __forceinline__ float softplusf(float x) {
    return fmaxf(x, 0.0f) + __logf(1.0f + __expf(-fabsf(x)));
}
__device__ __forceinline__ float sigmoidf(float x) {
    return __fdividef(1.0f, 1.0f + __expf(-x));
}

// ---------------- embedding: x = atom_fea @ emb_W + emb_b ----------------
__global__ __launch_bounds__(256) void k_embed(
    const float* __restrict__ atom_fea,
    const float* __restrict__ W,   // (92,64)
    const float* __restrict__ b)
{
    __shared__ float W_sh[ORIG*AF];
    __shared__ float a_sh[4][ORIG];
    int tid = threadIdx.x;
    for (int i = tid; i < ORIG*AF; i += 256) W_sh[i] = W[i];
    int r0 = blockIdx.x * 4;
    for (int i = tid; i < 4*ORIG; i += 256) {
        int r = i / ORIG, k = i % ORIG;
        a_sh[r][k] = atom_fea[(r0 + r)*ORIG + k];
    }
    __syncthreads();
    int rl = tid >> 6;
    int c  = tid & 63;
    float acc = b[c];
    #pragma unroll 4
    for (int k = 0; k < ORIG; k++) acc += a_sh[rl][k] * W_sh[k*AF + c];
    d_x[(r0 + rl)*AF + c] = acc;
}

// ---------------- zero BN accumulators ----------------
__global__ void k_zero_stats() {
    int t = threadIdx.x;
    if (t < TWOAF) { d_s1[t] = 0.f; d_q1[t] = 0.f; }
    if (t < AF)    { d_s2[t] = 0.f; d_q2[t] = 0.f; }
}

// ---------------- edge GEMM (persistent) + fused BN1 stats ----------------
// Persistent blocks: stage W once, loop over 32-edge tiles.
// Thread tile: 4 edges x 4 cols. tot stored transposed [k][edge] for float4 A loads.
// lane map: rg = lane&7 (row group), cg = warp*4 + (lane>>3) (col group 0..31)
__global__ __launch_bounds__(256) void k_edge_gemm(
    const float* __restrict__ nbr_fea,   // (N,M,41)
    const int*   __restrict__ nbr_idx,   // (N,M)
    const float* __restrict__ Wc,        // (169,128)
    const float* __restrict__ bc)        // (128)
{
    extern __shared__ float sh[];
    float* W_sh   = sh;                   // 169*128
    float* tot_sh = sh + KTOT*TWOAF;      // 169*32, transposed [k][el]
    __shared__ int   nb_sh[32];
    __shared__ int   at_sh[32];

    int tid = threadIdx.x;
    int w   = tid >> 5;
    int l   = tid & 31;
    int rg  = l & 7;
    int cg  = (w << 2) | (l >> 3);     // 0..31

    // stage W once
    {
        const float4* Wv = (const float4*)Wc;
        float4* Wsv = (float4*)W_sh;
        #pragma unroll 4
        for (int i = tid; i < KTOT*TWOAF/4; i += 256) Wsv[i] = Wv[i];
    }

    float4 bv = *(const float4*)&bc[cg*4];

    // per-block column stat accumulators (lane rg==0 owns cols cg*4..cg*4+3)
    float sacc0=0.f,sacc1=0.f,sacc2=0.f,sacc3=0.f;
    float qacc0=0.f,qacc1=0.f,qacc2=0.f,qacc3=0.f;

    for (int tile = blockIdx.x; tile < NTILES; tile += gridDim.x) {
        int e0 = tile * 32;
        __syncthreads();   // previous compute done before restaging
        if (tid < 32) {
            nb_sh[tid] = nbr_idx[e0 + tid];
            at_sh[tid] = (e0 + tid) / MNBR;
        }
        __syncthreads();
        // stage tot transposed: i = k*32 + el (consecutive threads -> consecutive el)
        for (int i = tid; i < KTOT*32; i += 256) {
            int k  = i >> 5;
            int el = i & 31;
            float v;
            if (k < AF)        v = d_x[at_sh[el]*AF + k];
            else if (k < 2*AF) v = d_x[nb_sh[el]*AF + (k - AF)];
            else               v = nbr_fea[(size_t)(e0 + el)*NBRF + (k - 2*AF)];
            tot_sh[i] = v;
        }
        __syncthreads();

        float acc[4][4];
        #pragma unroll
        for (int i = 0; i < 4; i++)
            #pragma unroll
            for (int j = 0; j < 4; j++) acc[i][j] = 0.f;

        const float* tp = tot_sh + rg*4;
        const float* wp = W_sh + cg*4;
        #pragma unroll 2
        for (int k = 0; k < KTOT; k++) {
            float4 av = *(const float4*)(tp + k*32);
            float4 wv = *(const float4*)(wp + k*TWOAF);
            acc[0][0] += av.x*wv.x; acc[0][1] += av.x*wv.y; acc[0][2] += av.x*wv.z; acc[0][3] += av.x*wv.w;
            acc[1][0] += av.y*wv.x; acc[1][1] += av.y*wv.y; acc[1][2] += av.y*wv.z; acc[1][3] += av.y*wv.w;
            acc[2][0] += av.z*wv.x; acc[2][1] += av.z*wv.y; acc[2][2] += av.z*wv.z; acc[2][3] += av.z*wv.w;
            acc[3][0] += av.w*wv.x; acc[3][1] += av.w*wv.y; acc[3][2] += av.w*wv.z; acc[3][3] += av.w*wv.w;
        }

        // bias + store + column stats
        float s0=0.f,s1=0.f,s2=0.f,s3=0.f,q0=0.f,q1=0.f,q2=0.f,q3=0.f;
        #pragma unroll
        for (int i = 0; i < 4; i++) {
            float g0 = acc[i][0] + bv.x;
            float g1 = acc[i][1] + bv.y;
            float g2 = acc[i][2] + bv.z;
            float g3 = acc[i][3] + bv.w;
            s0 += g0; s1 += g1; s2 += g2; s3 += g3;
            q0 += g0*g0; q1 += g1*g1; q2 += g2*g2; q3 += g3*g3;
            int e = e0 + rg*4 + i;
            *(float4*)&d_g[(size_t)e*TWOAF + cg*4] = make_float4(g0, g1, g2, g3);
        }
        // butterfly reduce over rg (low 3 bits of lane)
        #pragma unroll
        for (int m = 1; m < 8; m <<= 1) {
            s0 += __shfl_xor_sync(0xffffffffu, s0, m);
            s1 += __shfl_xor_sync(0xffffffffu, s1, m);
            s2 += __shfl_xor_sync(0xffffffffu, s2, m);
            s3 += __shfl_xor_sync(0xffffffffu, s3, m);
            q0 += __shfl_xor_sync(0xffffffffu, q0, m);
            q1 += __shfl_xor_sync(0xffffffffu, q1, m);
            q2 += __shfl_xor_sync(0xffffffffu, q2, m);
            q3 += __shfl_xor_sync(0xffffffffu, q3, m);
        }
        if (rg == 0) {
            sacc0 += s0; sacc1 += s1; sacc2 += s2; sacc3 += s3;
            qacc0 += q0; qacc1 += q1; qacc2 += q2; qacc3 += q3;
        }
    }

    if (rg == 0) {
        atomicAdd(&d_s1[cg*4+0], sacc0); atomicAdd(&d_s1[cg*4+1], sacc1);
        atomicAdd(&d_s1[cg*4+2], sacc2); atomicAdd(&d_s1[cg*4+3], sacc3);
        atomicAdd(&d_q1[cg*4+0], qacc0); atomicAdd(&d_q1[cg*4+1], qacc1);
        atomicAdd(&d_q1[cg*4+2], qacc2); atomicAdd(&d_q1[cg*4+3], qacc3);
    }
}

__global__ void k_fin1(const float* __restrict__ g1, const float* __restrict__ b1) {
    int c = threadIdx.x;   // 128
    float inv_n = 1.0f / (float)EDGES;
    float mu  = d_s1[c] * inv_n;
    float var = d_q1[c] * inv_n - mu*mu;
    float sc  = rsqrtf(var + BNEPS) * g1[c];
    d_scale1[c] = sc;
    d_shift1[c] = b1[c] - mu * sc;
}

// ---------------- gate + sum over neighbors, BN2 stats ----------------
__global__ __launch_bounds__(256) void k_gate_sum() {
    __shared__ float s2_sh[AF], q2_sh[AF];
    int tid = threadIdx.x;
    if (tid < AF) { s2_sh[tid] = 0.f; q2_sh[tid] = 0.f; }
    __syncthreads();

    int al = tid >> 6, c = tid & 63;
    int a  = blockIdx.x*4 + al;
    float sc_f = d_scale1[c],      sh_f = d_shift1[c];
    float sc_s = d_scale1[c + AF], sh_s = d_shift1[c + AF];

    float acc = 0.f;
    size_t base = (size_t)a * MNBR * TWOAF;
    #pragma unroll
    for (int m = 0; m < MNBR; m++) {
        float f = d_g[base + m*TWOAF + c]      * sc_f + sh_f;
        float s = d_g[base + m*TWOAF + c + AF] * sc_s + sh_s;
        acc += sigmoidf(f) * softplusf(s);
    }
    d_summed[a*AF + c] = acc;
    atomicAdd(&s2_sh[c], acc);
    atomicAdd(&q2_sh[c], acc*acc);
    __syncthreads();
    if (tid < AF) {
        atomicAdd(&d_s2[tid], s2_sh[tid]);
        atomicAdd(&d_q2[tid], q2_sh[tid]);
    }
}

__global__ void k_fin2(const float* __restrict__ g2, const float* __restrict__ b2) {
    int c = threadIdx.x;  // 64
    float inv_n = 1.0f / (float)NATOMS;
    float mu  = d_s2[c] * inv_n;
    float var = d_q2[c] * inv_n - mu*mu;
    float sc  = rsqrtf(var + BNEPS) * g2[c];
    d_scale2[c] = sc;
    d_shift2[c] = b2[c] - mu * sc;
}

// ---------------- residual update: x = softplus(x + BN2(summed)) ----------------
__global__ __launch_bounds__(256) void k_update_x() {
    int i = blockIdx.x*256 + threadIdx.x;
    int c = i & (AF-1);
    float v = d_summed[i] * d_scale2[c] + d_shift2[c];
    d_x[i] = softplusf(d_x[i] + v);
}

// ---------------- pool + head MLP ----------------
__global__ __launch_bounds__(128) void k_head(
    const float* __restrict__ fc1W, const float* __restrict__ fc1b,
    const float* __restrict__ fc2W, const float* __restrict__ fc2b,
    const float* __restrict__ outW, const float* __restrict__ outb,
    float* __restrict__ out)
{
    __shared__ float p[AF];
    __shared__ float h1[HF];
    __shared__ float red[HF];
    int tid = threadIdx.x;
    int b = blockIdx.x;

    if (tid < AF) {
        const float* xb = &d_x[(size_t)b * ATOMS_PER * AF];
        float s = 0.f;
        #pragma unroll
        for (int a = 0; a < ATOMS_PER; a++) s += xb[a*AF + tid];
        p[tid] = softplusf(s * (1.0f/ATOMS_PER));
    }
    __syncthreads();

    float acc = fc1b[tid];
    #pragma unroll 4
    for (int k = 0; k < AF; k++) acc += p[k] * fc1W[k*HF + tid];
    h1[tid] = softplusf(acc);
    __syncthreads();

    float acc2 = fc2b[tid];
    #pragma unroll 4
    for (int k = 0; k < HF; k++) acc2 += h1[k] * fc2W[k*HF + tid];
    float h2 = softplusf(acc2);

    red[tid] = h2 * outW[tid];
    __syncthreads();
    for (int s = HF/2; s > 0; s >>= 1) {
        if (tid < s) red[tid] += red[tid + s];
        __syncthreads();
    }
    if (tid == 0) out[b] = red[0] + outb[0];
}

// ---------------- launch ----------------
extern "C" void kernel_launch(void* const* d_in, const int* in_sizes, int n_in,
                              void* d_out, int out_size)
{
    const float* atom_fea = (const float*)d_in[0];
    const float* nbr_fea  = (const float*)d_in[1];
    const int*   nbr_idx  = (const int*)  d_in[2];
    const float* embW  = (const float*)d_in[4];
    const float* embB  = (const float*)d_in[5];
    const float* convW = (const float*)d_in[6];
    const float* convB = (const float*)d_in[7];
    const float* bn1g  = (const float*)d_in[8];
    const float* bn1b  = (const float*)d_in[9];
    const float* bn2g  = (const float*)d_in[10];
    const float* bn2b  = (const float*)d_in[11];
    const float* fc1W  = (const float*)d_in[12];
    const float* fc1b  = (const float*)d_in[13];
    const float* fc2W  = (const float*)d_in[14];
    const float* fc2b  = (const float*)d_in[15];
    const float* outW  = (const float*)d_in[16];
    const float* outb  = (const float*)d_in[17];
    float* out = (float*)d_out;

    const int smem_gemm = (KTOT*TWOAF + KTOT*32) * (int)sizeof(float);  // 108160 B
    cudaFuncSetAttribute(k_edge_gemm, cudaFuncAttributeMaxDynamicSharedMemorySize, smem_gemm);

    k_embed<<<NATOMS/4, 256>>>(atom_fea, embW, embB);

    for (int l = 0; l < NCONV; l++) {
        k_zero_stats<<<1, 256>>>();
        k_edge_gemm<<<296, 256, smem_gemm>>>(nbr_fea, nbr_idx,
                                             convW + (size_t)l*KTOT*TWOAF,
                                             convB + l*TWOAF);
        k_fin1<<<1, 128>>>(bn1g + l*TWOAF, bn1b + l*TWOAF);
        k_gate_sum<<<NATOMS/4, 256>>>();
        k_fin2<<<1, 64>>>(bn2g + l*AF, bn2b + l*AF);
        k_update_x<<<NATOMS*AF/256, 256>>>();
    }

    k_head<<<NCRYS, 128>>>(fc1W, fc1b, fc2W, fc2b, outW, outb, out);
}

// round 8
// speedup vs baseline: 4.6174x; 2.5622x over previous
#include <cuda_runtime.h>
#include <cuda_bf16.h>
#include <cuda_fp16.h>
#include <math.h>

#define NATOMS 32768
#define MNBR   12
#define ORIG   92
#define NBRF   41
#define AF     64
#define TWOAF  128
#define KTOT   (2*AF + NBRF)   // 169
#define EDGES  (NATOMS*MNBR)   // 393216
#define NTILES (EDGES/32)      // 12288
#define NCONV  3
#define ATOMS_PER 32
#define NCRYS  (NATOMS/ATOMS_PER)  // 1024
#define HF     128
#define BNEPS  1e-5f

// ---------------- scratch (device globals: allocation-free) ----------------
__device__ float d_x[NATOMS*AF];                   // atom features (8.4 MB)
__device__ float d_Pself[(size_t)NATOMS*TWOAF];    // x@W_self + b  (16.8 MB, L2-resident)
__device__ float d_Pnbr [(size_t)NATOMS*TWOAF];    // x@W_nbr       (16.8 MB, L2-resident)
__device__ __half d_gh[(size_t)EDGES*TWOAF];       // edge pre-activations fp16 (100 MB)
__device__ float d_summed[NATOMS*AF];
__device__ float d_s1[TWOAF], d_q1[TWOAF];
__device__ float d_scale1[TWOAF], d_shift1[TWOAF];
__device__ float d_s2[AF], d_q2[AF];
__device__ float d_scale2[AF], d_shift2[AF];

__device__ __forceinline__ float softplusf(float x) {
    return fmaxf(x, 0.0f) + __logf(1.0f + __expf(-fabsf(x)));
}
__device__ __forceinline__ float sigmoidf(float x) {
    return __fdividef(1.0f, 1.0f + __expf(-x));
}

// ---------------- embedding: x = atom_fea @ emb_W + emb_b ----------------
__global__ __launch_bounds__(256) void k_embed(
    const float* __restrict__ atom_fea,
    const float* __restrict__ W,
    const float* __restrict__ b)
{
    __shared__ float W_sh[ORIG*AF];
    __shared__ float a_sh[4][ORIG];
    int tid = threadIdx.x;
    for (int i = tid; i < ORIG*AF; i += 256) W_sh[i] = W[i];
    int r0 = blockIdx.x * 4;
    for (int i = tid; i < 4*ORIG; i += 256) {
        int r = i / ORIG, k = i % ORIG;
        a_sh[r][k] = atom_fea[(r0 + r)*ORIG + k];
    }
    __syncthreads();
    int rl = tid >> 6;
    int c  = tid & 63;
    float acc = b[c];
    #pragma unroll 4
    for (int k = 0; k < ORIG; k++) acc += a_sh[rl][k] * W_sh[k*AF + c];
    d_x[(r0 + rl)*AF + c] = acc;
}

__global__ void k_zero_stats() {
    int t = threadIdx.x;
    if (t < TWOAF) { d_s1[t] = 0.f; d_q1[t] = 0.f; }
    if (t < AF)    { d_s2[t] = 0.f; d_q2[t] = 0.f; }
}

// ---------------- atom-level precompute: P_self = x@W[0:64]+b, P_nbr = x@W[64:128] ----------------
// block = 32 atoms x 256 cols (self 128 | nbr 128). thread tile 4 atoms x 8 cols.
__global__ __launch_bounds__(256) void k_atom_pre(
    const float* __restrict__ Wc,   // (169,128), rows 0..127 used here
    const float* __restrict__ bc)   // (128)
{
    extern __shared__ float sh[];
    float* W_sh = sh;              // 64*256  [k][c] with c<128 self, c>=128 nbr
    float* x_sh = sh + 64*256;     // 64*32   [k][a]
    int tid = threadIdx.x;
    int a0  = blockIdx.x * 32;

    // stage W: row k cols 0..127 from Wc row k; cols 128..255 from Wc row 64+k
    {
        const float4* Wv = (const float4*)Wc;
        float4* Wsv = (float4*)W_sh;
        for (int i = tid; i < 64*64; i += 256) {
            int kv = i >> 6, cv = i & 63;
            Wsv[i] = (cv < 32) ? Wv[kv*32 + cv] : Wv[(64 + kv)*32 + (cv - 32)];
        }
    }
    for (int i = tid; i < 64*32; i += 256) {
        int k = i >> 5, a = i & 31;
        x_sh[i] = d_x[(a0 + a)*AF + k];
    }
    __syncthreads();

    int w  = tid >> 5, l = tid & 31;
    int rg = l & 7;
    int cg = (w << 2) | (l >> 3);   // 0..31, cols cg*8..cg*8+7

    float acc[4][8];
    #pragma unroll
    for (int i = 0; i < 4; i++)
        #pragma unroll
        for (int j = 0; j < 8; j++) acc[i][j] = 0.f;

    const float* tp = x_sh + rg*4;
    const float* wp = W_sh + cg*8;
    #pragma unroll 4
    for (int k = 0; k < AF; k++) {
        float4 av = *(const float4*)(tp + k*32);
        float4 w0 = *(const float4*)(wp + k*256);
        float4 w1 = *(const float4*)(wp + k*256 + 4);
        float a4[4] = {av.x, av.y, av.z, av.w};
        #pragma unroll
        for (int i = 0; i < 4; i++) {
            acc[i][0] += a4[i]*w0.x; acc[i][1] += a4[i]*w0.y;
            acc[i][2] += a4[i]*w0.z; acc[i][3] += a4[i]*w0.w;
            acc[i][4] += a4[i]*w1.x; acc[i][5] += a4[i]*w1.y;
            acc[i][6] += a4[i]*w1.z; acc[i][7] += a4[i]*w1.w;
        }
    }

    if (cg < 16) {
        int c0 = cg*8;
        float4 bv0 = *(const float4*)&bc[c0];
        float4 bv1 = *(const float4*)&bc[c0 + 4];
        #pragma unroll
        for (int i = 0; i < 4; i++) {
            int a = a0 + rg*4 + i;
            *(float4*)&d_Pself[(size_t)a*TWOAF + c0] =
                make_float4(acc[i][0]+bv0.x, acc[i][1]+bv0.y, acc[i][2]+bv0.z, acc[i][3]+bv0.w);
            *(float4*)&d_Pself[(size_t)a*TWOAF + c0 + 4] =
                make_float4(acc[i][4]+bv1.x, acc[i][5]+bv1.y, acc[i][6]+bv1.z, acc[i][7]+bv1.w);
        }
    } else {
        int c0 = cg*8 - TWOAF;
        #pragma unroll
        for (int i = 0; i < 4; i++) {
            int a = a0 + rg*4 + i;
            *(float4*)&d_Pnbr[(size_t)a*TWOAF + c0] =
                make_float4(acc[i][0], acc[i][1], acc[i][2], acc[i][3]);
            *(float4*)&d_Pnbr[(size_t)a*TWOAF + c0 + 4] =
                make_float4(acc[i][4], acc[i][5], acc[i][6], acc[i][7]);
        }
    }
}

// ---------------- edge kernel: g = P_self[a] + P_nbr[nb] + nbr_fea@W_edge; fp16 store + BN1 stats ----------------
__global__ __launch_bounds__(256) void k_edge(
    const float* __restrict__ nbr_fea,   // (N,M,41)
    const int*   __restrict__ nbr_idx,   // (N,M)
    const float* __restrict__ We)        // (41,128) = conv_W rows 128..168
{
    __shared__ float W_sh[NBRF*TWOAF];   // 20.5 KB
    __shared__ float tot_sh[NBRF*32];    // 5.25 KB, [k][el]
    __shared__ int nb_sh[32];
    __shared__ int at_sh[32];

    int tid = threadIdx.x;
    int w   = tid >> 5, l = tid & 31;
    int rg  = l & 7;
    int cg  = (w << 2) | (l >> 3);

    {
        const float4* Wv = (const float4*)We;
        float4* Wsv = (float4*)W_sh;
        for (int i = tid; i < NBRF*TWOAF/4; i += 256) Wsv[i] = Wv[i];
    }

    float sacc0=0.f,sacc1=0.f,sacc2=0.f,sacc3=0.f;
    float qacc0=0.f,qacc1=0.f,qacc2=0.f,qacc3=0.f;

    for (int tile = blockIdx.x; tile < NTILES; tile += gridDim.x) {
        int e0 = tile * 32;
        __syncthreads();
        if (tid < 32) {
            nb_sh[tid] = nbr_idx[e0 + tid];
            at_sh[tid] = (e0 + tid) / MNBR;
        }
        for (int i = tid; i < NBRF*32; i += 256) {
            int k  = i >> 5;
            int el = i & 31;
            tot_sh[i] = nbr_fea[(size_t)(e0 + el)*NBRF + k];
        }
        __syncthreads();

        float acc[4][4];
        #pragma unroll
        for (int i = 0; i < 4; i++)
            #pragma unroll
            for (int j = 0; j < 4; j++) acc[i][j] = 0.f;

        const float* tp = tot_sh + rg*4;
        const float* wp = W_sh + cg*4;
        #pragma unroll 4
        for (int k = 0; k < NBRF; k++) {
            float4 av = *(const float4*)(tp + k*32);
            float4 wv = *(const float4*)(wp + k*TWOAF);
            acc[0][0] += av.x*wv.x; acc[0][1] += av.x*wv.y; acc[0][2] += av.x*wv.z; acc[0][3] += av.x*wv.w;
            acc[1][0] += av.y*wv.x; acc[1][1] += av.y*wv.y; acc[1][2] += av.y*wv.z; acc[1][3] += av.y*wv.w;
            acc[2][0] += av.z*wv.x; acc[2][1] += av.z*wv.y; acc[2][2] += av.z*wv.z; acc[2][3] += av.z*wv.w;
            acc[3][0] += av.w*wv.x; acc[3][1] += av.w*wv.y; acc[3][2] += av.w*wv.z; acc[3][3] += av.w*wv.w;
        }

        float s0=0.f,s1=0.f,s2=0.f,s3=0.f,q0=0.f,q1=0.f,q2=0.f,q3=0.f;
        #pragma unroll
        for (int i = 0; i < 4; i++) {
            int el = rg*4 + i;
            int e  = e0 + el;
            float4 ps = *(const float4*)&d_Pself[(size_t)at_sh[el]*TWOAF + cg*4];
            float4 pn = *(const float4*)&d_Pnbr [(size_t)nb_sh[el]*TWOAF + cg*4];
            float g0 = acc[i][0] + ps.x + pn.x;
            float g1 = acc[i][1] + ps.y + pn.y;
            float g2 = acc[i][2] + ps.z + pn.z;
            float g3 = acc[i][3] + ps.w + pn.w;
            s0 += g0; s1 += g1; s2 += g2; s3 += g3;
            q0 += g0*g0; q1 += g1*g1; q2 += g2*g2; q3 += g3*g3;
            __half2 h01 = __floats2half2_rn(g0, g1);
            __half2 h23 = __floats2half2_rn(g2, g3);
            uint2 st;
            st.x = *reinterpret_cast<unsigned int*>(&h01);
            st.y = *reinterpret_cast<unsigned int*>(&h23);
            *reinterpret_cast<uint2*>(&d_gh[(size_t)e*TWOAF + cg*4]) = st;
        }
        #pragma unroll
        for (int m = 1; m < 8; m <<= 1) {
            s0 += __shfl_xor_sync(0xffffffffu, s0, m);
            s1 += __shfl_xor_sync(0xffffffffu, s1, m);
            s2 += __shfl_xor_sync(0xffffffffu, s2, m);
            s3 += __shfl_xor_sync(0xffffffffu, s3, m);
            q0 += __shfl_xor_sync(0xffffffffu, q0, m);
            q1 += __shfl_xor_sync(0xffffffffu, q1, m);
            q2 += __shfl_xor_sync(0xffffffffu, q2, m);
            q3 += __shfl_xor_sync(0xffffffffu, q3, m);
        }
        if (rg == 0) {
            sacc0 += s0; sacc1 += s1; sacc2 += s2; sacc3 += s3;
            qacc0 += q0; qacc1 += q1; qacc2 += q2; qacc3 += q3;
        }
    }

    if (rg == 0) {
        atomicAdd(&d_s1[cg*4+0], sacc0); atomicAdd(&d_s1[cg*4+1], sacc1);
        atomicAdd(&d_s1[cg*4+2], sacc2); atomicAdd(&d_s1[cg*4+3], sacc3);
        atomicAdd(&d_q1[cg*4+0], qacc0); atomicAdd(&d_q1[cg*4+1], qacc1);
        atomicAdd(&d_q1[cg*4+2], qacc2); atomicAdd(&d_q1[cg*4+3], qacc3);
    }
}

__global__ void k_fin1(const float* __restrict__ g1, const float* __restrict__ b1) {
    int c = threadIdx.x;   // 128
    float inv_n = 1.0f / (float)EDGES;
    float mu  = d_s1[c] * inv_n;
    float var = d_q1[c] * inv_n - mu*mu;
    float sc  = rsqrtf(var + BNEPS) * g1[c];
    d_scale1[c] = sc;
    d_shift1[c] = b1[c] - mu * sc;
}

// ---------------- gate + sum (fp16 input), BN2 stats ----------------
// block = 8 atoms x 32 threads; thread covers 2 cols via half2
__global__ __launch_bounds__(256) void k_gate_sum() {
    __shared__ float s2_sh[AF], q2_sh[AF];
    int tid = threadIdx.x;
    if (tid < AF) { s2_sh[tid] = 0.f; q2_sh[tid] = 0.f; }
    __syncthreads();

    int al = tid >> 5, c2 = tid & 31;
    int c0 = c2 * 2;
    int a  = blockIdx.x*8 + al;

    float2 scf = *(const float2*)&d_scale1[c0];
    float2 shf = *(const float2*)&d_shift1[c0];
    float2 scs = *(const float2*)&d_scale1[AF + c0];
    float2 shs = *(const float2*)&d_shift1[AF + c0];

    float ax = 0.f, ay = 0.f;
    size_t base = (size_t)a * MNBR * TWOAF;
    #pragma unroll
    for (int m = 0; m < MNBR; m++) {
        float2 f = __half22float2(*(const __half2*)&d_gh[base + m*TWOAF + c0]);
        float2 s = __half22float2(*(const __half2*)&d_gh[base + m*TWOAF + AF + c0]);
        float fx = f.x*scf.x + shf.x, fy = f.y*scf.y + shf.y;
        float sx = s.x*scs.x + shs.x, sy = s.y*scs.y + shs.y;
        ax += sigmoidf(fx) * softplusf(sx);
        ay += sigmoidf(fy) * softplusf(sy);
    }
    *(float2*)&d_summed[a*AF + c0] = make_float2(ax, ay);
    atomicAdd(&s2_sh[c0],   ax);
    atomicAdd(&s2_sh[c0+1], ay);
    atomicAdd(&q2_sh[c0],   ax*ax);
    atomicAdd(&q2_sh[c0+1], ay*ay);
    __syncthreads();
    if (tid < AF) {
        atomicAdd(&d_s2[tid], s2_sh[tid]);
        atomicAdd(&d_q2[tid], q2_sh[tid]);
    }
}

__global__ void k_fin2(const float* __restrict__ g2, const float* __restrict__ b2) {
    int c = threadIdx.x;  // 64
    float inv_n = 1.0f / (float)NATOMS;
    float mu  = d_s2[c] * inv_n;
    float var = d_q2[c] * inv_n - mu*mu;
    float sc  = rsqrtf(var + BNEPS) * g2[c];
    d_scale2[c] = sc;
    d_shift2[c] = b2[c] - mu * sc;
}

__global__ __launch_bounds__(256) void k_update_x() {
    int i = blockIdx.x*256 + threadIdx.x;
    int c = i & (AF-1);
    float v = d_summed[i] * d_scale2[c] + d_shift2[c];
    d_x[i] = softplusf(d_x[i] + v);
}

// ---------------- pool + head MLP ----------------
__global__ __launch_bounds__(128) void k_head(
    const float* __restrict__ fc1W, const float* __restrict__ fc1b,
    const float* __restrict__ fc2W, const float* __restrict__ fc2b,
    const float* __restrict__ outW, const float* __restrict__ outb,
    float* __restrict__ out)
{
    __shared__ float p[AF];
    __shared__ float h1[HF];
    __shared__ float red[HF];
    int tid = threadIdx.x;
    int b = blockIdx.x;

    if (tid < AF) {
        const float* xb = &d_x[(size_t)b * ATOMS_PER * AF];
        float s = 0.f;
        #pragma unroll
        for (int a = 0; a < ATOMS_PER; a++) s += xb[a*AF + tid];
        p[tid] = softplusf(s * (1.0f/ATOMS_PER));
    }
    __syncthreads();

    float acc = fc1b[tid];
    #pragma unroll 4
    for (int k = 0; k < AF; k++) acc += p[k] * fc1W[k*HF + tid];
    h1[tid] = softplusf(acc);
    __syncthreads();

    float acc2 = fc2b[tid];
    #pragma unroll 4
    for (int k = 0; k < HF; k++) acc2 += h1[k] * fc2W[k*HF + tid];
    float h2 = softplusf(acc2);

    red[tid] = h2 * outW[tid];
    __syncthreads();
    for (int s = HF/2; s > 0; s >>= 1) {
        if (tid < s) red[tid] += red[tid + s];
        __syncthreads();
    }
    if (tid == 0) out[b] = red[0] + outb[0];
}

// ---------------- launch ----------------
extern "C" void kernel_launch(void* const* d_in, const int* in_sizes, int n_in,
                              void* d_out, int out_size)
{
    const float* atom_fea = (const float*)d_in[0];
    const float* nbr_fea  = (const float*)d_in[1];
    const int*   nbr_idx  = (const int*)  d_in[2];
    const float* embW  = (const float*)d_in[4];
    const float* embB  = (const float*)d_in[5];
    const float* convW = (const float*)d_in[6];
    const float* convB = (const float*)d_in[7];
    const float* bn1g  = (const float*)d_in[8];
    const float* bn1b  = (const float*)d_in[9];
    const float* bn2g  = (const float*)d_in[10];
    const float* bn2b  = (const float*)d_in[11];
    const float* fc1W  = (const float*)d_in[12];
    const float* fc1b  = (const float*)d_in[13];
    const float* fc2W  = (const float*)d_in[14];
    const float* fc2b  = (const float*)d_in[15];
    const float* outW  = (const float*)d_in[16];
    const float* outb  = (const float*)d_in[17];
    float* out = (float*)d_out;

    const int smem_pre = (64*256 + 64*32) * (int)sizeof(float);  // 73728 B
    cudaFuncSetAttribute(k_atom_pre, cudaFuncAttributeMaxDynamicSharedMemorySize, smem_pre);

    k_embed<<<NATOMS/4, 256>>>(atom_fea, embW, embB);

    for (int l = 0; l < NCONV; l++) {
        k_zero_stats<<<1, 256>>>();
        const float* Wl = convW + (size_t)l*KTOT*TWOAF;
        k_atom_pre<<<NATOMS/32, 256, smem_pre>>>(Wl, convB + l*TWOAF);
        k_edge<<<592, 256>>>(nbr_fea, nbr_idx, Wl + (size_t)TWOAF*TWOAF);
        k_fin1<<<1, 128>>>(bn1g + l*TWOAF, bn1b + l*TWOAF);
        k_gate_sum<<<NATOMS/8, 256>>>();
        k_fin2<<<1, 64>>>(bn2g + l*AF, bn2b + l*AF);
        k_update_x<<<NATOMS*AF/256, 256>>>();
    }

    k_head<<<NCRYS, 128>>>(fc1W, fc1b, fc2W, fc2b, outW, outb, out);
}

// round 9
// speedup vs baseline: 4.8820x; 1.0573x over previous
#include <cuda_runtime.h>
#include <cuda_bf16.h>
#include <cuda_fp16.h>
#include <math.h>

#define NATOMS 32768
#define MNBR   12
#define ORIG   92
#define NBRF   41
#define AF     64
#define TWOAF  128
#define KTOT   (2*AF + NBRF)   // 169
#define EDGES  (NATOMS*MNBR)   // 393216
#define NT64   (EDGES/64)      // 6144
#define NCONV  3
#define ATOMS_PER 32
#define NCRYS  (NATOMS/ATOMS_PER)
#define HF     128
#define BNEPS  1e-5f

// ---------------- scratch ----------------
__device__ float  d_x[NATOMS*AF];
__device__ __half d_Psh[(size_t)NATOMS*TWOAF];   // x@W_self + b (fp16, 8.4 MB)
__device__ __half d_Pnh[(size_t)NATOMS*TWOAF];   // x@W_nbr      (fp16, 8.4 MB)
__device__ __half d_gh[(size_t)EDGES*TWOAF];     // edge pre-activations (100 MB)
__device__ float  d_summed[NATOMS*AF];
__device__ float  d_s1[TWOAF], d_q1[TWOAF];
__device__ float  d_scale1[TWOAF], d_shift1[TWOAF];
__device__ float  d_s2[AF], d_q2[AF];
__device__ float  d_scale2[AF], d_shift2[AF];

__device__ __forceinline__ float softplusf(float x) {
    return fmaxf(x, 0.0f) + __logf(1.0f + __expf(-fabsf(x)));
}
__device__ __forceinline__ float sigmoidf(float x) {
    return __fdividef(1.0f, 1.0f + __expf(-x));
}

__device__ __forceinline__ void cp_async4(void* smem_dst, const void* gptr) {
    unsigned sa = (unsigned)__cvta_generic_to_shared(smem_dst);
    asm volatile("cp.async.ca.shared.global [%0], [%1], 4;" :: "r"(sa), "l"(gptr));
}
__device__ __forceinline__ void cp_commit() { asm volatile("cp.async.commit_group;"); }
__device__ __forceinline__ void cp_wait0()  { asm volatile("cp.async.wait_group 0;"); }

// ---------------- embedding ----------------
__global__ __launch_bounds__(256) void k_embed(
    const float* __restrict__ atom_fea,
    const float* __restrict__ W,
    const float* __restrict__ b)
{
    __shared__ float W_sh[ORIG*AF];
    __shared__ float a_sh[4][ORIG];
    int tid = threadIdx.x;
    for (int i = tid; i < ORIG*AF; i += 256) W_sh[i] = W[i];
    int r0 = blockIdx.x * 4;
    for (int i = tid; i < 4*ORIG; i += 256) {
        int r = i / ORIG, k = i % ORIG;
        a_sh[r][k] = atom_fea[(r0 + r)*ORIG + k];
    }
    __syncthreads();
    int rl = tid >> 6;
    int c  = tid & 63;
    float acc = b[c];
    #pragma unroll 4
    for (int k = 0; k < ORIG; k++) acc += a_sh[rl][k] * W_sh[k*AF + c];
    d_x[(r0 + rl)*AF + c] = acc;
}

__global__ void k_zero_stats() {
    int t = threadIdx.x;
    if (t < TWOAF) { d_s1[t] = 0.f; d_q1[t] = 0.f; }
    if (t < AF)    { d_s2[t] = 0.f; d_q2[t] = 0.f; }
}

// ---------------- atom precompute -> fp16 P tables ----------------
// block = 32 atoms x 256 cols (self 128 | nbr 128), thread tile 4 atoms x 8 cols
__global__ __launch_bounds__(256) void k_atom_pre(
    const float* __restrict__ Wc,   // (169,128)
    const float* __restrict__ bc)
{
    extern __shared__ float sh[];
    float* W_sh = sh;              // 64*256
    float* x_sh = sh + 64*256;     // 64*32
    int tid = threadIdx.x;
    int a0  = blockIdx.x * 32;

    {
        const float4* Wv = (const float4*)Wc;
        float4* Wsv = (float4*)W_sh;
        for (int i = tid; i < 64*64; i += 256) {
            int kv = i >> 6, cv = i & 63;
            Wsv[i] = (cv < 32) ? Wv[kv*32 + cv] : Wv[(64 + kv)*32 + (cv - 32)];
        }
    }
    for (int i = tid; i < 64*32; i += 256) {
        int k = i >> 5, a = i & 31;
        x_sh[i] = d_x[(a0 + a)*AF + k];
    }
    __syncthreads();

    int w  = tid >> 5, l = tid & 31;
    int rg = l & 7;
    int cg = (w << 2) | (l >> 3);

    float acc[4][8];
    #pragma unroll
    for (int i = 0; i < 4; i++)
        #pragma unroll
        for (int j = 0; j < 8; j++) acc[i][j] = 0.f;

    const float* tp = x_sh + rg*4;
    const float* wp = W_sh + cg*8;
    #pragma unroll 4
    for (int k = 0; k < AF; k++) {
        float4 av = *(const float4*)(tp + k*32);
        float4 w0 = *(const float4*)(wp + k*256);
        float4 w1 = *(const float4*)(wp + k*256 + 4);
        float a4[4] = {av.x, av.y, av.z, av.w};
        #pragma unroll
        for (int i = 0; i < 4; i++) {
            acc[i][0] += a4[i]*w0.x; acc[i][1] += a4[i]*w0.y;
            acc[i][2] += a4[i]*w0.z; acc[i][3] += a4[i]*w0.w;
            acc[i][4] += a4[i]*w1.x; acc[i][5] += a4[i]*w1.y;
            acc[i][6] += a4[i]*w1.z; acc[i][7] += a4[i]*w1.w;
        }
    }

    bool is_self = (cg < 16);
    int c0 = is_self ? cg*8 : cg*8 - TWOAF;
    float b8[8];
    #pragma unroll
    for (int j = 0; j < 8; j++) b8[j] = is_self ? bc[c0 + j] : 0.f;
    __half* dst = is_self ? d_Psh : d_Pnh;
    #pragma unroll
    for (int i = 0; i < 4; i++) {
        int a = a0 + rg*4 + i;
        __half2 h[4];
        #pragma unroll
        for (int j = 0; j < 4; j++)
            h[j] = __floats2half2_rn(acc[i][2*j] + b8[2*j], acc[i][2*j+1] + b8[2*j+1]);
        uint4 st;
        st.x = *(unsigned*)&h[0]; st.y = *(unsigned*)&h[1];
        st.z = *(unsigned*)&h[2]; st.w = *(unsigned*)&h[3];
        *reinterpret_cast<uint4*>(&dst[(size_t)a*TWOAF + c0]) = st;
    }
}

// ---------------- edge kernel: 64-edge tiles, 4x8 thread tile, cp.async double buffer ----------------
__global__ __launch_bounds__(256) void k_edge(
    const float* __restrict__ nbr_fea,   // (N,M,41)
    const int*   __restrict__ nbr_idx,   // (N,M)
    const float* __restrict__ We)        // (41,128)
{
    __shared__ float W_sh[NBRF*TWOAF];       // 20992 B
    __shared__ float A_sh[2][NBRF*64];       // 2 x 10496 B, [k][el]
    __shared__ float s_st[TWOAF], q_st[TWOAF];

    int tid = threadIdx.x;
    int eg  = tid & 15;        // edge group: edges eg*4..+3
    int cg  = tid >> 4;        // col group: cols cg*8..+7

    {
        const float4* Wv = (const float4*)We;
        float4* Wsv = (float4*)W_sh;
        for (int i = tid; i < NBRF*TWOAF/4; i += 256) Wsv[i] = Wv[i];
    }
    if (tid < TWOAF) { s_st[tid] = 0.f; q_st[tid] = 0.f; }

    // prologue: stage first tile into buf 0
    int tile0 = blockIdx.x;
    if (tile0 < NT64) {
        const float* src = nbr_fea + (size_t)tile0*64*NBRF;
        for (int i = tid; i < 64*NBRF; i += 256) {
            int el = i / NBRF, k = i - el*NBRF;
            cp_async4(&A_sh[0][k*64 + el], src + i);
        }
    }
    cp_commit();

    int buf = 0;
    for (int tile = tile0; tile < NT64; tile += gridDim.x) {
        cp_wait0();
        __syncthreads();
        int ntile = tile + gridDim.x;
        if (ntile < NT64) {
            const float* src = nbr_fea + (size_t)ntile*64*NBRF;
            float* dst = A_sh[buf^1];
            for (int i = tid; i < 64*NBRF; i += 256) {
                int el = i / NBRF, k = i - el*NBRF;
                cp_async4(&dst[k*64 + el], src + i);
            }
        }
        cp_commit();

        // GEMM: 4 edges x 8 cols per thread
        float acc[4][8];
        #pragma unroll
        for (int i = 0; i < 4; i++)
            #pragma unroll
            for (int j = 0; j < 8; j++) acc[i][j] = 0.f;

        const float* tp = A_sh[buf] + eg*4;
        const float* wp = W_sh + cg*8;
        #pragma unroll 4
        for (int k = 0; k < NBRF; k++) {
            float4 av = *(const float4*)(tp + k*64);
            float4 w0 = *(const float4*)(wp + k*TWOAF);
            float4 w1 = *(const float4*)(wp + k*TWOAF + 4);
            float a4[4] = {av.x, av.y, av.z, av.w};
            #pragma unroll
            for (int i = 0; i < 4; i++) {
                acc[i][0] += a4[i]*w0.x; acc[i][1] += a4[i]*w0.y;
                acc[i][2] += a4[i]*w0.z; acc[i][3] += a4[i]*w0.w;
                acc[i][4] += a4[i]*w1.x; acc[i][5] += a4[i]*w1.y;
                acc[i][6] += a4[i]*w1.z; acc[i][7] += a4[i]*w1.w;
            }
        }

        // epilogue: gather fp16 P, stats, fp16 store
        int e_base = tile*64 + eg*4;
        int4 nbv = *(const int4*)&nbr_idx[e_base];
        int nbs[4] = {nbv.x, nbv.y, nbv.z, nbv.w};
        float s8[8], q8[8];
        #pragma unroll
        for (int j = 0; j < 8; j++) { s8[j] = 0.f; q8[j] = 0.f; }

        #pragma unroll
        for (int i = 0; i < 4; i++) {
            int e = e_base + i;
            int a = e / MNBR;
            uint4 psv = *reinterpret_cast<const uint4*>(&d_Psh[(size_t)a*TWOAF + cg*8]);
            uint4 pnv = *reinterpret_cast<const uint4*>(&d_Pnh[(size_t)nbs[i]*TWOAF + cg*8]);
            float ps[8], pn[8];
            {
                float2 t;
                t = __half22float2(*(__half2*)&psv.x); ps[0]=t.x; ps[1]=t.y;
                t = __half22float2(*(__half2*)&psv.y); ps[2]=t.x; ps[3]=t.y;
                t = __half22float2(*(__half2*)&psv.z); ps[4]=t.x; ps[5]=t.y;
                t = __half22float2(*(__half2*)&psv.w); ps[6]=t.x; ps[7]=t.y;
                t = __half22float2(*(__half2*)&pnv.x); pn[0]=t.x; pn[1]=t.y;
                t = __half22float2(*(__half2*)&pnv.y); pn[2]=t.x; pn[3]=t.y;
                t = __half22float2(*(__half2*)&pnv.z); pn[4]=t.x; pn[5]=t.y;
                t = __half22float2(*(__half2*)&pnv.w); pn[6]=t.x; pn[7]=t.y;
            }
            float g[8];
            #pragma unroll
            for (int j = 0; j < 8; j++) {
                g[j] = acc[i][j] + ps[j] + pn[j];
                s8[j] += g[j];
                q8[j] += g[j]*g[j];
            }
            __half2 h[4];
            #pragma unroll
            for (int j = 0; j < 4; j++) h[j] = __floats2half2_rn(g[2*j], g[2*j+1]);
            uint4 st;
            st.x = *(unsigned*)&h[0]; st.y = *(unsigned*)&h[1];
            st.z = *(unsigned*)&h[2]; st.w = *(unsigned*)&h[3];
            *reinterpret_cast<uint4*>(&d_gh[(size_t)e*TWOAF + cg*8]) = st;
        }

        // butterfly over eg (lanes l and l^m share cg for m<16)
        #pragma unroll
        for (int m = 1; m < 16; m <<= 1) {
            #pragma unroll
            for (int j = 0; j < 8; j++) {
                s8[j] += __shfl_xor_sync(0xffffffffu, s8[j], m);
                q8[j] += __shfl_xor_sync(0xffffffffu, q8[j], m);
            }
        }
        if (eg == 0) {
            #pragma unroll
            for (int j = 0; j < 8; j++) {
                atomicAdd(&s_st[cg*8 + j], s8[j]);
                atomicAdd(&q_st[cg*8 + j], q8[j]);
            }
        }
        buf ^= 1;
    }

    __syncthreads();
    if (tid < TWOAF) {
        atomicAdd(&d_s1[tid], s_st[tid]);
        atomicAdd(&d_q1[tid], q_st[tid]);
    }
}

__global__ void k_fin1(const float* __restrict__ g1, const float* __restrict__ b1) {
    int c = threadIdx.x;   // 128
    float inv_n = 1.0f / (float)EDGES;
    float mu  = d_s1[c] * inv_n;
    float var = d_q1[c] * inv_n - mu*mu;
    float sc  = rsqrtf(var + BNEPS) * g1[c];
    d_scale1[c] = sc;
    d_shift1[c] = b1[c] - mu * sc;
}

// ---------------- gate + sum (fp16 input), BN2 stats ----------------
__global__ __launch_bounds__(256) void k_gate_sum() {
    __shared__ float s2_sh[AF], q2_sh[AF];
    int tid = threadIdx.x;
    if (tid < AF) { s2_sh[tid] = 0.f; q2_sh[tid] = 0.f; }
    __syncthreads();

    int al = tid >> 5, c2 = tid & 31;
    int c0 = c2 * 2;
    int a  = blockIdx.x*8 + al;

    float2 scf = *(const float2*)&d_scale1[c0];
    float2 shf = *(const float2*)&d_shift1[c0];
    float2 scs = *(const float2*)&d_scale1[AF + c0];
    float2 shs = *(const float2*)&d_shift1[AF + c0];

    float ax = 0.f, ay = 0.f;
    size_t base = (size_t)a * MNBR * TWOAF;
    #pragma unroll
    for (int m = 0; m < MNBR; m++) {
        float2 f = __half22float2(*(const __half2*)&d_gh[base + m*TWOAF + c0]);
        float2 s = __half22float2(*(const __half2*)&d_gh[base + m*TWOAF + AF + c0]);
        float fx = f.x*scf.x + shf.x, fy = f.y*scf.y + shf.y;
        float sx = s.x*scs.x + shs.x, sy = s.y*scs.y + shs.y;
        ax += sigmoidf(fx) * softplusf(sx);
        ay += sigmoidf(fy) * softplusf(sy);
    }
    *(float2*)&d_summed[a*AF + c0] = make_float2(ax, ay);
    atomicAdd(&s2_sh[c0],   ax);
    atomicAdd(&s2_sh[c0+1], ay);
    atomicAdd(&q2_sh[c0],   ax*ax);
    atomicAdd(&q2_sh[c0+1], ay*ay);
    __syncthreads();
    if (tid < AF) {
        atomicAdd(&d_s2[tid], s2_sh[tid]);
        atomicAdd(&d_q2[tid], q2_sh[tid]);
    }
}

__global__ void k_fin2(const float* __restrict__ g2, const float* __restrict__ b2) {
    int c = threadIdx.x;  // 64
    float inv_n = 1.0f / (float)NATOMS;
    float mu  = d_s2[c] * inv_n;
    float var = d_q2[c] * inv_n - mu*mu;
    float sc  = rsqrtf(var + BNEPS) * g2[c];
    d_scale2[c] = sc;
    d_shift2[c] = b2[c] - mu * sc;
}

__global__ __launch_bounds__(256) void k_update_x() {
    int i = blockIdx.x*256 + threadIdx.x;
    int c = i & (AF-1);
    float v = d_summed[i] * d_scale2[c] + d_shift2[c];
    d_x[i] = softplusf(d_x[i] + v);
}

// ---------------- pool + head MLP ----------------
__global__ __launch_bounds__(128) void k_head(
    const float* __restrict__ fc1W, const float* __restrict__ fc1b,
    const float* __restrict__ fc2W, const float* __restrict__ fc2b,
    const float* __restrict__ outW, const float* __restrict__ outb,
    float* __restrict__ out)
{
    __shared__ float p[AF];
    __shared__ float h1[HF];
    __shared__ float red[HF];
    int tid = threadIdx.x;
    int b = blockIdx.x;

    if (tid < AF) {
        const float* xb = &d_x[(size_t)b * ATOMS_PER * AF];
        float s = 0.f;
        #pragma unroll
        for (int a = 0; a < ATOMS_PER; a++) s += xb[a*AF + tid];
        p[tid] = softplusf(s * (1.0f/ATOMS_PER));
    }
    __syncthreads();

    float acc = fc1b[tid];
    #pragma unroll 4
    for (int k = 0; k < AF; k++) acc += p[k] * fc1W[k*HF + tid];
    h1[tid] = softplusf(acc);
    __syncthreads();

    float acc2 = fc2b[tid];
    #pragma unroll 4
    for (int k = 0; k < HF; k++) acc2 += h1[k] * fc2W[k*HF + tid];
    float h2 = softplusf(acc2);

    red[tid] = h2 * outW[tid];
    __syncthreads();
    for (int s = HF/2; s > 0; s >>= 1) {
        if (tid < s) red[tid] += red[tid + s];
        __syncthreads();
    }
    if (tid == 0) out[b] = red[0] + outb[0];
}

// ---------------- launch ----------------
extern "C" void kernel_launch(void* const* d_in, const int* in_sizes, int n_in,
                              void* d_out, int out_size)
{
    const float* atom_fea = (const float*)d_in[0];
    const float* nbr_fea  = (const float*)d_in[1];
    const int*   nbr_idx  = (const int*)  d_in[2];
    const float* embW  = (const float*)d_in[4];
    const float* embB  = (const float*)d_in[5];
    const float* convW = (const float*)d_in[6];
    const float* convB = (const float*)d_in[7];
    const float* bn1g  = (const float*)d_in[8];
    const float* bn1b  = (const float*)d_in[9];
    const float* bn2g  = (const float*)d_in[10];
    const float* bn2b  = (const float*)d_in[11];
    const float* fc1W  = (const float*)d_in[12];
    const float* fc1b  = (const float*)d_in[13];
    const float* fc2W  = (const float*)d_in[14];
    const float* fc2b  = (const float*)d_in[15];
    const float* outW  = (const float*)d_in[16];
    const float* outb  = (const float*)d_in[17];
    float* out = (float*)d_out;

    const int smem_pre = (64*256 + 64*32) * (int)sizeof(float);
    cudaFuncSetAttribute(k_atom_pre, cudaFuncAttributeMaxDynamicSharedMemorySize, smem_pre);

    k_embed<<<NATOMS/4, 256>>>(atom_fea, embW, embB);

    for (int l = 0; l < NCONV; l++) {
        k_zero_stats<<<1, 256>>>();
        const float* Wl = convW + (size_t)l*KTOT*TWOAF;
        k_atom_pre<<<NATOMS/32, 256, smem_pre>>>(Wl, convB + l*TWOAF);
        k_edge<<<444, 256>>>(nbr_fea, nbr_idx, Wl + (size_t)TWOAF*TWOAF);
        k_fin1<<<1, 128>>>(bn1g + l*TWOAF, bn1b + l*TWOAF);
        k_gate_sum<<<NATOMS/8, 256>>>();
        k_fin2<<<1, 64>>>(bn2g + l*AF, bn2b + l*AF);
        k_update_x<<<NATOMS*AF/256, 256>>>();
    }

    k_head<<<NCRYS, 128>>>(fc1W, fc1b, fc2W, fc2b, outW, outb, out);
}

// round 12
// speedup vs baseline: 6.7182x; 1.3761x over previous
#include <cuda_runtime.h>
#include <cuda_bf16.h>
#include <cuda_fp16.h>
#include <math.h>

#define NATOMS 32768
#define MNBR   12
#define ORIG   92
#define NBRF   41
#define KPAD   48
#define AF     64
#define TWOAF  128
#define KTOT   (2*AF + NBRF)   // 169
#define EDGES  (NATOMS*MNBR)   // 393216
#define NT64   (EDGES/64)      // 6144
#define NCONV  3
#define ATOMS_PER 32
#define NCRYS  (NATOMS/ATOMS_PER)
#define HF     128
#define BNEPS  1e-5f

// ---------------- scratch ----------------
__device__ float  d_x[NATOMS*AF];
__device__ __half d_Psh[(size_t)NATOMS*TWOAF];   // x@W_self + b (fp16)
__device__ __half d_Pnh[(size_t)NATOMS*TWOAF];   // x@W_nbr (fp16)
__device__ __half d_gh[(size_t)EDGES*TWOAF];     // edge pre-activations (100 MB)
__device__ uint4  d_Ah[(size_t)(EDGES/16)*3*32]; // nbr_fea as A-fragments (37.7 MB)
__device__ __half d_Weh[KPAD*TWOAF];             // W_edge fp16, K padded to 48
__device__ float  d_summed[NATOMS*AF];
__device__ float  d_s1[TWOAF], d_q1[TWOAF];
__device__ float  d_scale1[TWOAF], d_shift1[TWOAF];
__device__ float  d_s2[AF], d_q2[AF];
__device__ float  d_scale2[AF], d_shift2[AF];

__device__ __forceinline__ float softplusf(float x) {
    return fmaxf(x, 0.0f) + __logf(1.0f + __expf(-fabsf(x)));
}
__device__ __forceinline__ float sigmoidf(float x) {
    return __fdividef(1.0f, 1.0f + __expf(-x));
}

// ---------------- embedding ----------------
__global__ __launch_bounds__(256) void k_embed(
    const float* __restrict__ atom_fea,
    const float* __restrict__ W,
    const float* __restrict__ b)
{
    __shared__ float W_sh[ORIG*AF];
    __shared__ float a_sh[4][ORIG];
    int tid = threadIdx.x;
    for (int i = tid; i < ORIG*AF; i += 256) W_sh[i] = W[i];
    int r0 = blockIdx.x * 4;
    for (int i = tid; i < 4*ORIG; i += 256) {
        int r = i / ORIG, k = i % ORIG;
        a_sh[r][k] = atom_fea[(r0 + r)*ORIG + k];
    }
    __syncthreads();
    int rl = tid >> 6;
    int c  = tid & 63;
    float acc = b[c];
    #pragma unroll 4
    for (int k = 0; k < ORIG; k++) acc += a_sh[rl][k] * W_sh[k*AF + c];
    d_x[(r0 + rl)*AF + c] = acc;
}

__global__ void k_zero_stats() {
    int t = threadIdx.x;
    if (t < TWOAF) { d_s1[t] = 0.f; d_q1[t] = 0.f; }
    if (t < AF)    { d_s2[t] = 0.f; d_q2[t] = 0.f; }
}

// ---------------- one-time: nbr_fea -> fragment-swizzled fp16 A buffer ----------------
// thread = (etile16, ks, lane) -> 8 halfs = lane's A-fragment for mma.m16n8k16
__global__ __launch_bounds__(256) void k_cvt_nbr(const float* __restrict__ nbr_fea)
{
    int idx  = blockIdx.x*256 + threadIdx.x;   // < (E/16)*3*32 = 2359296
    int lane = idx & 31;
    int ks   = (idx >> 5) % 3;
    int t    = idx / 96;
    int r0 = t*16 + (lane >> 2);
    int c0 = ks*16 + (lane & 3)*2;

    float v[8];
    #pragma unroll
    for (int j = 0; j < 8; j++) {
        int r = r0 + ((j >> 1) & 1) * 8;          // j=0,1,4,5 -> r0 ; j=2,3,6,7 -> r0+8
        int c = c0 + (j & 1) + (j >> 2) * 8;      // j>=4 -> +8
        v[j] = (c < NBRF) ? nbr_fea[(size_t)r*NBRF + c] : 0.f;
    }
    __half2 h0 = __floats2half2_rn(v[0], v[1]);
    __half2 h1 = __floats2half2_rn(v[2], v[3]);
    __half2 h2 = __floats2half2_rn(v[4], v[5]);
    __half2 h3 = __floats2half2_rn(v[6], v[7]);
    uint4 st;
    st.x = *(unsigned*)&h0; st.y = *(unsigned*)&h1;
    st.z = *(unsigned*)&h2; st.w = *(unsigned*)&h3;
    d_Ah[idx] = st;
}

// ---------------- per-layer: W_edge -> fp16 padded ----------------
__global__ __launch_bounds__(256) void k_cvt_W(const float* __restrict__ We) // (41,128)
{
    int idx = blockIdx.x*256 + threadIdx.x;    // < 48*128
    int k = idx >> 7, n = idx & 127;
    d_Weh[idx] = __float2half((k < NBRF) ? We[k*TWOAF + n] : 0.f);
}

// ---------------- atom precompute -> fp16 P tables ----------------
__global__ __launch_bounds__(256) void k_atom_pre(
    const float* __restrict__ Wc,   // (169,128)
    const float* __restrict__ bc)
{
    extern __shared__ float sh[];
    float* W_sh = sh;              // 64*256
    float* x_sh = sh + 64*256;     // 64*32
    int tid = threadIdx.x;
    int a0  = blockIdx.x * 32;

    {
        const float4* Wv = (const float4*)Wc;
        float4* Wsv = (float4*)W_sh;
        for (int i = tid; i < 64*64; i += 256) {
            int kv = i >> 6, cv = i & 63;
            Wsv[i] = (cv < 32) ? Wv[kv*32 + cv] : Wv[(64 + kv)*32 + (cv - 32)];
        }
    }
    for (int i = tid; i < 64*32; i += 256) {
        int k = i >> 5, a = i & 31;
        x_sh[i] = d_x[(a0 + a)*AF + k];
    }
    __syncthreads();

    int w  = tid >> 5, l = tid & 31;
    int rg = l & 7;
    int cg = (w << 2) | (l >> 3);

    float acc[4][8];
    #pragma unroll
    for (int i = 0; i < 4; i++)
        #pragma unroll
        for (int j = 0; j < 8; j++) acc[i][j] = 0.f;

    const float* tp = x_sh + rg*4;
    const float* wp = W_sh + cg*8;
    #pragma unroll 4
    for (int k = 0; k < AF; k++) {
        float4 av = *(const float4*)(tp + k*32);
        float4 w0 = *(const float4*)(wp + k*256);
        float4 w1 = *(const float4*)(wp + k*256 + 4);
        float a4[4] = {av.x, av.y, av.z, av.w};
        #pragma unroll
        for (int i = 0; i < 4; i++) {
            acc[i][0] += a4[i]*w0.x; acc[i][1] += a4[i]*w0.y;
            acc[i][2] += a4[i]*w0.z; acc[i][3] += a4[i]*w0.w;
            acc[i][4] += a4[i]*w1.x; acc[i][5] += a4[i]*w1.y;
            acc[i][6] += a4[i]*w1.z; acc[i][7] += a4[i]*w1.w;
        }
    }

    bool is_self = (cg < 16);
    int c0 = is_self ? cg*8 : cg*8 - TWOAF;
    float b8[8];
    #pragma unroll
    for (int j = 0; j < 8; j++) b8[j] = is_self ? bc[c0 + j] : 0.f;
    __half* dst = is_self ? d_Psh : d_Pnh;
    #pragma unroll
    for (int i = 0; i < 4; i++) {
        int a = a0 + rg*4 + i;
        __half2 h[4];
        #pragma unroll
        for (int j = 0; j < 4; j++)
            h[j] = __floats2half2_rn(acc[i][2*j] + b8[2*j], acc[i][2*j+1] + b8[2*j+1]);
        uint4 st;
        st.x = *(unsigned*)&h[0]; st.y = *(unsigned*)&h[1];
        st.z = *(unsigned*)&h[2]; st.w = *(unsigned*)&h[3];
        *reinterpret_cast<uint4*>(&dst[(size_t)a*TWOAF + c0]) = st;
    }
}

// ---------------- edge kernel: HMMA GEMM + gather epilogue + fused BN1 stats ----------------
// persistent; block tile = 64 edges x 128 cols; warp w covers cols w*16..+15
__global__ __launch_bounds__(256, 2) void k_edge_mma(
    const int* __restrict__ nbr_idx)
{
    __shared__ __half C_sh[64*136];
    __shared__ int nb_sh[64];

    int tid  = threadIdx.x;
    int warp = tid >> 5;
    int lane = tid & 31;
    int eg   = tid & 15;
    int cg   = tid >> 4;

    // preload B fragments (W fixed for whole kernel): 2 ntiles x 3 ksteps x 2 regs
    unsigned bfrag[2][3][2];
    {
        int nb_ = warp*16 + (lane >> 2);
        #pragma unroll
        for (int nt = 0; nt < 2; nt++) {
            int n = nb_ + nt*8;
            #pragma unroll
            for (int ks = 0; ks < 3; ks++) {
                int k0 = ks*16 + (lane & 3)*2;
                __half2 b0 = __halves2half2(d_Weh[k0*TWOAF + n],     d_Weh[(k0+1)*TWOAF + n]);
                __half2 b1 = __halves2half2(d_Weh[(k0+8)*TWOAF + n], d_Weh[(k0+9)*TWOAF + n]);
                bfrag[nt][ks][0] = *(unsigned*)&b0;
                bfrag[nt][ks][1] = *(unsigned*)&b1;
            }
        }
    }

    float s8[8], q8[8];
    #pragma unroll
    for (int j = 0; j < 8; j++) { s8[j] = 0.f; q8[j] = 0.f; }

    int r    = lane >> 2;
    int ncol = warp*16 + (lane & 3)*2;

    for (int tile = blockIdx.x; tile < NT64; tile += gridDim.x) {
        __syncthreads();   // C_sh / nb_sh free (prev epilogue done)
        if (tid < 16) *(int4*)&nb_sh[tid*4] = *(const int4*)&nbr_idx[tile*64 + tid*4];

        float acc[4][2][4];
        #pragma unroll
        for (int mt = 0; mt < 4; mt++)
            #pragma unroll
            for (int nt = 0; nt < 2; nt++)
                #pragma unroll
                for (int j = 0; j < 4; j++) acc[mt][nt][j] = 0.f;

        #pragma unroll
        for (int ks = 0; ks < 3; ks++) {
            #pragma unroll
            for (int mt = 0; mt < 4; mt++) {
                uint4 a = d_Ah[(size_t)((tile*4 + mt)*3 + ks)*32 + lane];
                #pragma unroll
                for (int nt = 0; nt < 2; nt++) {
                    asm volatile(
                        "mma.sync.aligned.m16n8k16.row.col.f32.f16.f16.f32 "
                        "{%0,%1,%2,%3}, {%4,%5,%6,%7}, {%8,%9}, {%0,%1,%2,%3};\n"
                        : "+f"(acc[mt][nt][0]), "+f"(acc[mt][nt][1]),
                          "+f"(acc[mt][nt][2]), "+f"(acc[mt][nt][3])
                        : "r"(a.x), "r"(a.y), "r"(a.z), "r"(a.w),
                          "r"(bfrag[nt][ks][0]), "r"(bfrag[nt][ks][1]));
                }
            }
        }

        // store accumulators to C_sh (fp16, conflict-free STS.32)
        #pragma unroll
        for (int mt = 0; mt < 4; mt++)
            #pragma unroll
            for (int nt = 0; nt < 2; nt++) {
                __half2 h01 = __floats2half2_rn(acc[mt][nt][0], acc[mt][nt][1]);
                __half2 h23 = __floats2half2_rn(acc[mt][nt][2], acc[mt][nt][3]);
                *(__half2*)&C_sh[(mt*16 + r)*136 + ncol + nt*8]       = h01;
                *(__half2*)&C_sh[(mt*16 + r + 8)*136 + ncol + nt*8]   = h23;
            }
        __syncthreads();

        // epilogue: strided edges (eg + 16i), cols cg*8..+7
        #pragma unroll
        for (int i = 0; i < 4; i++) {
            int el = eg + 16*i;
            int e  = tile*64 + el;
            int a_ = e / MNBR;
            int nb = nb_sh[el];
            uint4 cvv = *(const uint4*)&C_sh[el*136 + cg*8];
            uint4 psv = *reinterpret_cast<const uint4*>(&d_Psh[(size_t)a_*TWOAF + cg*8]);
            uint4 pnv = *reinterpret_cast<const uint4*>(&d_Pnh[(size_t)nb*TWOAF + cg*8]);
            const __half2* ch = (const __half2*)&cvv;
            const __half2* ph = (const __half2*)&psv;
            const __half2* nh = (const __half2*)&pnv;
            float g[8];
            #pragma unroll
            for (int p = 0; p < 4; p++) {
                float2 cf = __half22float2(ch[p]);
                float2 pf = __half22float2(ph[p]);
                float2 nf = __half22float2(nh[p]);
                g[2*p]   = cf.x + pf.x + nf.x;
                g[2*p+1] = cf.y + pf.y + nf.y;
            }
            #pragma unroll
            for (int j = 0; j < 8; j++) { s8[j] += g[j]; q8[j] += g[j]*g[j]; }
            __half2 h[4];
            #pragma unroll
            for (int p = 0; p < 4; p++) h[p] = __floats2half2_rn(g[2*p], g[2*p+1]);
            uint4 st;
            st.x = *(unsigned*)&h[0]; st.y = *(unsigned*)&h[1];
            st.z = *(unsigned*)&h[2]; st.w = *(unsigned*)&h[3];
            *reinterpret_cast<uint4*>(&d_gh[(size_t)e*TWOAF + cg*8]) = st;
        }
    }

    // final stats reduce over eg (low 4 lane bits within same cg) + global atomics
    #pragma unroll
    for (int m = 1; m < 16; m <<= 1) {
        #pragma unroll
        for (int j = 0; j < 8; j++) {
            s8[j] += __shfl_xor_sync(0xffffffffu, s8[j], m);
            q8[j] += __shfl_xor_sync(0xffffffffu, q8[j], m);
        }
    }
    if (eg == 0) {
        #pragma unroll
        for (int j = 0; j < 8; j++) {
            atomicAdd(&d_s1[cg*8 + j], s8[j]);
            atomicAdd(&d_q1[cg*8 + j], q8[j]);
        }
    }
}

__global__ void k_fin1(const float* __restrict__ g1, const float* __restrict__ b1) {
    int c = threadIdx.x;   // 128
    float inv_n = 1.0f / (float)EDGES;
    float mu  = d_s1[c] * inv_n;
    float var = d_q1[c] * inv_n - mu*mu;
    float sc  = rsqrtf(var + BNEPS) * g1[c];
    d_scale1[c] = sc;
    d_shift1[c] = b1[c] - mu * sc;
}

// ---------------- gate + sum (fp16 input), BN2 stats ----------------
__global__ __launch_bounds__(256) void k_gate_sum() {
    __shared__ float s2_sh[AF], q2_sh[AF];
    int tid = threadIdx.x;
    if (tid < AF) { s2_sh[tid] = 0.f; q2_sh[tid] = 0.f; }
    __syncthreads();

    int al = tid >> 5, c2 = tid & 31;
    int c0 = c2 * 2;
    int a  = blockIdx.x*8 + al;

    float2 scf = *(const float2*)&d_scale1[c0];
    float2 shf = *(const float2*)&d_shift1[c0];
    float2 scs = *(const float2*)&d_scale1[AF + c0];
    float2 shs = *(const float2*)&d_shift1[AF + c0];

    float ax = 0.f, ay = 0.f;
    size_t base = (size_t)a * MNBR * TWOAF;
    #pragma unroll
    for (int m = 0; m < MNBR; m++) {
        float2 f = __half22float2(*(const __half2*)&d_gh[base + m*TWOAF + c0]);
        float2 s = __half22float2(*(const __half2*)&d_gh[base + m*TWOAF + AF + c0]);
        float fx = f.x*scf.x + shf.x, fy = f.y*scf.y + shf.y;
        float sx = s.x*scs.x + shs.x, sy = s.y*scs.y + shs.y;
        ax += sigmoidf(fx) * softplusf(sx);
        ay += sigmoidf(fy) * softplusf(sy);
    }
    *(float2*)&d_summed[a*AF + c0] = make_float2(ax, ay);
    atomicAdd(&s2_sh[c0],   ax);
    atomicAdd(&s2_sh[c0+1], ay);
    atomicAdd(&q2_sh[c0],   ax*ax);
    atomicAdd(&q2_sh[c0+1], ay*ay);
    __syncthreads();
    if (tid < AF) {
        atomicAdd(&d_s2[tid], s2_sh[tid]);
        atomicAdd(&d_q2[tid], q2_sh[tid]);
    }
}

__global__ void k_fin2(const float* __restrict__ g2, const float* __restrict__ b2) {
    int c = threadIdx.x;  // 64
    float inv_n = 1.0f / (float)NATOMS;
    float mu  = d_s2[c] * inv_n;
    float var = d_q2[c] * inv_n - mu*mu;
    float sc  = rsqrtf(var + BNEPS) * g2[c];
    d_scale2[c] = sc;
    d_shift2[c] = b2[c] - mu * sc;
}

__global__ __launch_bounds__(256) void k_update_x() {
    int i = blockIdx.x*256 + threadIdx.x;
    int c = i & (AF-1);
    float v = d_summed[i] * d_scale2[c] + d_shift2[c];
    d_x[i] = softplusf(d_x[i] + v);
}

// ---------------- pool + head MLP ----------------
__global__ __launch_bounds__(128) void k_head(
    const float* __restrict__ fc1W, const float* __restrict__ fc1b,
    const float* __restrict__ fc2W, const float* __restrict__ fc2b,
    const float* __restrict__ outW, const float* __restrict__ outb,
    float* __restrict__ out)
{
    __shared__ float p[AF];
    __shared__ float h1[HF];
    __shared__ float red[HF];
    int tid = threadIdx.x;
    int b = blockIdx.x;

    if (tid < AF) {
        const float* xb = &d_x[(size_t)b * ATOMS_PER * AF];
        float s = 0.f;
        #pragma unroll
        for (int a = 0; a < ATOMS_PER; a++) s += xb[a*AF + tid];
        p[tid] = softplusf(s * (1.0f/ATOMS_PER));
    }
    __syncthreads();

    float acc = fc1b[tid];
    #pragma unroll 4
    for (int k = 0; k < AF; k++) acc += p[k] * fc1W[k*HF + tid];
    h1[tid] = softplusf(acc);
    __syncthreads();

    float acc2 = fc2b[tid];
    #pragma unroll 4
    for (int k = 0; k < HF; k++) acc2 += h1[k] * fc2W[k*HF + tid];
    float h2 = softplusf(acc2);

    red[tid] = h2 * outW[tid];
    __syncthreads();
    for (int s = HF/2; s > 0; s >>= 1) {
        if (tid < s) red[tid] += red[tid + s];
        __syncthreads();
    }
    if (tid == 0) out[b] = red[0] + outb[0];
}

// ---------------- launch ----------------
extern "C" void kernel_launch(void* const* d_in, const int* in_sizes, int n_in,
                              void* d_out, int out_size)
{
    const float* atom_fea = (const float*)d_in[0];
    const float* nbr_fea  = (const float*)d_in[1];
    const int*   nbr_idx  = (const int*)  d_in[2];
    const float* embW  = (const float*)d_in[4];
    const float* embB  = (const float*)d_in[5];
    const float* convW = (const float*)d_in[6];
    const float* convB = (const float*)d_in[7];
    const float* bn1g  = (const float*)d_in[8];
    const float* bn1b  = (const float*)d_in[9];
    const float* bn2g  = (const float*)d_in[10];
    const float* bn2b  = (const float*)d_in[11];
    const float* fc1W  = (const float*)d_in[12];
    const float* fc1b  = (const float*)d_in[13];
    const float* fc2W  = (const float*)d_in[14];
    const float* fc2b  = (const float*)d_in[15];
    const float* outW  = (const float*)d_in[16];
    const float* outb  = (const float*)d_in[17];
    float* out = (float*)d_out;

    const int smem_pre = (64*256 + 64*32) * (int)sizeof(float);
    cudaFuncSetAttribute(k_atom_pre, cudaFuncAttributeMaxDynamicSharedMemorySize, smem_pre);

    k_embed<<<NATOMS/4, 256>>>(atom_fea, embW, embB);
    k_cvt_nbr<<<(EDGES/16)*3*32/256, 256>>>(nbr_fea);   // once: layer-invariant

    for (int l = 0; l < NCONV; l++) {
        k_zero_stats<<<1, 256>>>();
        const float* Wl = convW + (size_t)l*KTOT*TWOAF;
        k_atom_pre<<<NATOMS/32, 256, smem_pre>>>(Wl, convB + l*TWOAF);
        k_cvt_W<<<KPAD*TWOAF/256, 256>>>(Wl + (size_t)TWOAF*TWOAF);
        k_edge_mma<<<296, 256>>>(nbr_idx);
        k_fin1<<<1, 128>>>(bn1g + l*TWOAF, bn1b + l*TWOAF);
        k_gate_sum<<<NATOMS/8, 256>>>();
        k_fin2<<<1, 64>>>(bn2g + l*AF, bn2b + l*AF);
        k_update_x<<<NATOMS*AF/256, 256>>>();
    }

    k_head<<<NCRYS, 128>>>(fc1W, fc1b, fc2W, fc2b, outW, outb, out);
}

// round 13
// speedup vs baseline: 7.0564x; 1.0503x over previous
#include <cuda_runtime.h>
#include <cuda_bf16.h>
#include <cuda_fp16.h>
#include <math.h>

#define NATOMS 32768
#define MNBR   12
#define ORIG   92
#define NBRF   41
#define KPAD   48
#define AF     64
#define TWOAF  128
#define KTOT   (2*AF + NBRF)   // 169
#define EDGES  (NATOMS*MNBR)   // 393216
#define NT64   (EDGES/64)      // 6144
#define NCONV  3
#define ATOMS_PER 32
#define NCRYS  (NATOMS/ATOMS_PER)
#define HF     128
#define BNEPS  1e-5f

// ---------------- scratch ----------------
__device__ float  d_x[NATOMS*AF];
__device__ __half d_Psh[(size_t)NATOMS*TWOAF];   // x@W_self + b (fp16)
__device__ __half d_Pnh[(size_t)NATOMS*TWOAF];   // x@W_nbr (fp16)
__device__ __half d_gh[(size_t)EDGES*TWOAF];     // edge pre-activations (100 MB)
__device__ uint4  d_Ah[(size_t)(EDGES/16)*3*32]; // nbr_fea A-fragments (37.7 MB)
__device__ uint4  d_Axh[(NATOMS/16)*4*32];       // x A-fragments (4 MB)
__device__ __half d_Weh[KPAD*TWOAF];             // W_edge fp16 (K padded 48)
__device__ uint2  d_Wph[32*4*32];                // [Wself|Wnbr] B-fragments (K=64,N=256)
__device__ float  d_summed[NATOMS*AF];
__device__ float  d_s1[TWOAF], d_q1[TWOAF];
__device__ float  d_scale1[TWOAF], d_shift1[TWOAF];
__device__ float  d_s2[AF], d_q2[AF];
__device__ float  d_scale2[AF], d_shift2[AF];

__device__ __forceinline__ float softplusf(float x) {
    return fmaxf(x, 0.0f) + __logf(1.0f + __expf(-fabsf(x)));
}
__device__ __forceinline__ float sigmoidf(float x) {
    return __fdividef(1.0f, 1.0f + __expf(-x));
}

// ---------------- embedding ----------------
__global__ __launch_bounds__(256) void k_embed(
    const float* __restrict__ atom_fea,
    const float* __restrict__ W,
    const float* __restrict__ b)
{
    __shared__ float W_sh[ORIG*AF];
    __shared__ float a_sh[4][ORIG];
    int tid = threadIdx.x;
    for (int i = tid; i < ORIG*AF; i += 256) W_sh[i] = W[i];
    int r0 = blockIdx.x * 4;
    for (int i = tid; i < 4*ORIG; i += 256) {
        int r = i / ORIG, k = i % ORIG;
        a_sh[r][k] = atom_fea[(r0 + r)*ORIG + k];
    }
    __syncthreads();
    int rl = tid >> 6;
    int c  = tid & 63;
    float acc = b[c];
    #pragma unroll 4
    for (int k = 0; k < ORIG; k++) acc += a_sh[rl][k] * W_sh[k*AF + c];
    d_x[(r0 + rl)*AF + c] = acc;
}

__global__ void k_zero_stats() {
    int t = threadIdx.x;
    if (t < TWOAF) { d_s1[t] = 0.f; d_q1[t] = 0.f; }
    if (t < AF)    { d_s2[t] = 0.f; d_q2[t] = 0.f; }
}

// ---------------- one-time: nbr_fea -> A-fragment fp16 buffer ----------------
__global__ __launch_bounds__(256) void k_cvt_nbr(const float* __restrict__ nbr_fea)
{
    int idx  = blockIdx.x*256 + threadIdx.x;   // < (E/16)*3*32
    int lane = idx & 31;
    int ks   = (idx >> 5) % 3;
    int t    = idx / 96;
    int r0 = t*16 + (lane >> 2);
    int c0 = ks*16 + (lane & 3)*2;

    float v[8];
    #pragma unroll
    for (int j = 0; j < 8; j++) {
        int r = r0 + ((j >> 1) & 1) * 8;
        int c = c0 + (j & 1) + (j >> 2) * 8;
        v[j] = (c < NBRF) ? nbr_fea[(size_t)r*NBRF + c] : 0.f;
    }
    __half2 h0 = __floats2half2_rn(v[0], v[1]);
    __half2 h1 = __floats2half2_rn(v[2], v[3]);
    __half2 h2 = __floats2half2_rn(v[4], v[5]);
    __half2 h3 = __floats2half2_rn(v[6], v[7]);
    uint4 st;
    st.x = *(unsigned*)&h0; st.y = *(unsigned*)&h1;
    st.z = *(unsigned*)&h2; st.w = *(unsigned*)&h3;
    d_Ah[idx] = st;
}

// ---------------- per-layer: x -> A-fragment fp16 buffer ----------------
__global__ __launch_bounds__(256) void k_cvt_x()
{
    int idx  = blockIdx.x*256 + threadIdx.x;   // < (NATOMS/16)*4*32 = 262144
    int lane = idx & 31;
    int ks   = (idx >> 5) & 3;
    int t    = idx >> 7;
    int r0 = t*16 + (lane >> 2);
    int c0 = ks*16 + (lane & 3)*2;

    float v[8];
    #pragma unroll
    for (int j = 0; j < 8; j++) {
        int r = r0 + ((j >> 1) & 1) * 8;
        int c = c0 + (j & 1) + (j >> 2) * 8;
        v[j] = d_x[r*AF + c];
    }
    __half2 h0 = __floats2half2_rn(v[0], v[1]);
    __half2 h1 = __floats2half2_rn(v[2], v[3]);
    __half2 h2 = __floats2half2_rn(v[4], v[5]);
    __half2 h3 = __floats2half2_rn(v[6], v[7]);
    uint4 st;
    st.x = *(unsigned*)&h0; st.y = *(unsigned*)&h1;
    st.z = *(unsigned*)&h2; st.w = *(unsigned*)&h3;
    d_Axh[idx] = st;
}

// ---------------- per-layer: W_edge -> fp16 padded ----------------
__global__ __launch_bounds__(256) void k_cvt_W(const float* __restrict__ We)
{
    int idx = blockIdx.x*256 + threadIdx.x;    // < 48*128
    int k = idx >> 7, n = idx & 127;
    d_Weh[idx] = __float2half((k < NBRF) ? We[k*TWOAF + n] : 0.f);
}

// ---------------- per-layer: [W_self|W_nbr] -> B-fragment buffer ----------------
// index: ((nt*4 + ks)*32 + lane); n = nt*8 + (lane>>2); k0 = ks*16 + (lane&3)*2
__global__ __launch_bounds__(256) void k_cvt_Wp(const float* __restrict__ Wc)
{
    int idx  = blockIdx.x*256 + threadIdx.x;   // < 4096
    int lane = idx & 31;
    int ks   = (idx >> 5) & 3;
    int nt   = idx >> 7;                        // 0..31
    int n  = nt*8 + (lane >> 2);
    int k0 = ks*16 + (lane & 3)*2;

    float w00, w01, w10, w11;
    if (n < TWOAF) {
        w00 = Wc[(k0    )*TWOAF + n]; w01 = Wc[(k0 + 1)*TWOAF + n];
        w10 = Wc[(k0 + 8)*TWOAF + n]; w11 = Wc[(k0 + 9)*TWOAF + n];
    } else {
        int nn = n - TWOAF;
        w00 = Wc[(AF + k0    )*TWOAF + nn]; w01 = Wc[(AF + k0 + 1)*TWOAF + nn];
        w10 = Wc[(AF + k0 + 8)*TWOAF + nn]; w11 = Wc[(AF + k0 + 9)*TWOAF + nn];
    }
    __half2 b0 = __floats2half2_rn(w00, w01);
    __half2 b1 = __floats2half2_rn(w10, w11);
    uint2 st;
    st.x = *(unsigned*)&b0; st.y = *(unsigned*)&b1;
    d_Wph[idx] = st;
}

// ---------------- atom GEMM via HMMA: P_self / P_nbr ----------------
// block = 16 atoms x 256 cols; warp w covers cols w*32 (4 n8-tiles)
__global__ __launch_bounds__(256) void k_atom_mma(const float* __restrict__ bc)
{
    int tid  = threadIdx.x;
    int warp = tid >> 5;
    int lane = tid & 31;
    int atile = blockIdx.x;           // 16 atoms

    float acc[4][4];
    #pragma unroll
    for (int nt = 0; nt < 4; nt++)
        #pragma unroll
        for (int j = 0; j < 4; j++) acc[nt][j] = 0.f;

    #pragma unroll
    for (int ks = 0; ks < 4; ks++) {
        uint4 a = d_Axh[(atile*4 + ks)*32 + lane];
        #pragma unroll
        for (int nt = 0; nt < 4; nt++) {
            uint2 b = d_Wph[((warp*4 + nt)*4 + ks)*32 + lane];
            asm volatile(
                "mma.sync.aligned.m16n8k16.row.col.f32.f16.f16.f32 "
                "{%0,%1,%2,%3}, {%4,%5,%6,%7}, {%8,%9}, {%0,%1,%2,%3};\n"
                : "+f"(acc[nt][0]), "+f"(acc[nt][1]), "+f"(acc[nt][2]), "+f"(acc[nt][3])
                : "r"(a.x), "r"(a.y), "r"(a.z), "r"(a.w), "r"(b.x), "r"(b.y));
        }
    }

    int r  = lane >> 2;
    int a0 = atile * 16;
    bool self = (warp < 4);
    __half* dst = self ? d_Psh : d_Pnh;
    #pragma unroll
    for (int nt = 0; nt < 4; nt++) {
        int c = warp*32 + nt*8 + (lane & 3)*2;
        float b0 = 0.f, b1 = 0.f;
        if (self) { b0 = bc[c]; b1 = bc[c + 1]; }
        int cc = self ? c : c - TWOAF;
        __half2 h0 = __floats2half2_rn(acc[nt][0] + b0, acc[nt][1] + b1);
        __half2 h1 = __floats2half2_rn(acc[nt][2] + b0, acc[nt][3] + b1);
        *(__half2*)&dst[(size_t)(a0 + r    )*TWOAF + cc] = h0;
        *(__half2*)&dst[(size_t)(a0 + r + 8)*TWOAF + cc] = h1;
    }
}

// ---------------- edge kernel: HMMA GEMM + gather epilogue + fused BN1 stats ----------------
__global__ __launch_bounds__(256, 2) void k_edge_mma(
    const int* __restrict__ nbr_idx)
{
    __shared__ __half C_sh[64*136];
    __shared__ int nb_sh[64];

    int tid  = threadIdx.x;
    int warp = tid >> 5;
    int lane = tid & 31;
    int eg   = tid & 15;
    int cg   = tid >> 4;

    unsigned bfrag[2][3][2];
    {
        int nb_ = warp*16 + (lane >> 2);
        #pragma unroll
        for (int nt = 0; nt < 2; nt++) {
            int n = nb_ + nt*8;
            #pragma unroll
            for (int ks = 0; ks < 3; ks++) {
                int k0 = ks*16 + (lane & 3)*2;
                __half2 b0 = __halves2half2(d_Weh[k0*TWOAF + n],     d_Weh[(k0+1)*TWOAF + n]);
                __half2 b1 = __halves2half2(d_Weh[(k0+8)*TWOAF + n], d_Weh[(k0+9)*TWOAF + n]);
                bfrag[nt][ks][0] = *(unsigned*)&b0;
                bfrag[nt][ks][1] = *(unsigned*)&b1;
            }
        }
    }

    float s8[8], q8[8];
    #pragma unroll
    for (int j = 0; j < 8; j++) { s8[j] = 0.f; q8[j] = 0.f; }

    int r    = lane >> 2;
    int ncol = warp*16 + (lane & 3)*2;

    for (int tile = blockIdx.x; tile < NT64; tile += gridDim.x) {
        __syncthreads();
        if (tid < 16) *(int4*)&nb_sh[tid*4] = *(const int4*)&nbr_idx[tile*64 + tid*4];

        float acc[4][2][4];
        #pragma unroll
        for (int mt = 0; mt < 4; mt++)
            #pragma unroll
            for (int nt = 0; nt < 2; nt++)
                #pragma unroll
                for (int j = 0; j < 4; j++) acc[mt][nt][j] = 0.f;

        #pragma unroll
        for (int ks = 0; ks < 3; ks++) {
            #pragma unroll
            for (int mt = 0; mt < 4; mt++) {
                uint4 a = d_Ah[(size_t)((tile*4 + mt)*3 + ks)*32 + lane];
                #pragma unroll
                for (int nt = 0; nt < 2; nt++) {
                    asm volatile(
                        "mma.sync.aligned.m16n8k16.row.col.f32.f16.f16.f32 "
                        "{%0,%1,%2,%3}, {%4,%5,%6,%7}, {%8,%9}, {%0,%1,%2,%3};\n"
                        : "+f"(acc[mt][nt][0]), "+f"(acc[mt][nt][1]),
                          "+f"(acc[mt][nt][2]), "+f"(acc[mt][nt][3])
                        : "r"(a.x), "r"(a.y), "r"(a.z), "r"(a.w),
                          "r"(bfrag[nt][ks][0]), "r"(bfrag[nt][ks][1]));
                }
            }
        }

        #pragma unroll
        for (int mt = 0; mt < 4; mt++)
            #pragma unroll
            for (int nt = 0; nt < 2; nt++) {
                __half2 h01 = __floats2half2_rn(acc[mt][nt][0], acc[mt][nt][1]);
                __half2 h23 = __floats2half2_rn(acc[mt][nt][2], acc[mt][nt][3]);
                *(__half2*)&C_sh[(mt*16 + r)*136 + ncol + nt*8]     = h01;
                *(__half2*)&C_sh[(mt*16 + r + 8)*136 + ncol + nt*8] = h23;
            }
        __syncthreads();

        #pragma unroll
        for (int i = 0; i < 4; i++) {
            int el = eg + 16*i;
            int e  = tile*64 + el;
            int a_ = e / MNBR;
            int nb = nb_sh[el];
            uint4 cvv = *(const uint4*)&C_sh[el*136 + cg*8];
            uint4 psv = *reinterpret_cast<const uint4*>(&d_Psh[(size_t)a_*TWOAF + cg*8]);
            uint4 pnv = *reinterpret_cast<const uint4*>(&d_Pnh[(size_t)nb*TWOAF + cg*8]);
            const __half2* ch = (const __half2*)&cvv;
            const __half2* ph = (const __half2*)&psv;
            const __half2* nh = (const __half2*)&pnv;
            float g[8];
            #pragma unroll
            for (int p = 0; p < 4; p++) {
                float2 cf = __half22float2(ch[p]);
                float2 pf = __half22float2(ph[p]);
                float2 nf = __half22float2(nh[p]);
                g[2*p]   = cf.x + pf.x + nf.x;
                g[2*p+1] = cf.y + pf.y + nf.y;
            }
            #pragma unroll
            for (int j = 0; j < 8; j++) { s8[j] += g[j]; q8[j] += g[j]*g[j]; }
            __half2 h[4];
            #pragma unroll
            for (int p = 0; p < 4; p++) h[p] = __floats2half2_rn(g[2*p], g[2*p+1]);
            uint4 st;
            st.x = *(unsigned*)&h[0]; st.y = *(unsigned*)&h[1];
            st.z = *(unsigned*)&h[2]; st.w = *(unsigned*)&h[3];
            *reinterpret_cast<uint4*>(&d_gh[(size_t)e*TWOAF + cg*8]) = st;
        }
    }

    #pragma unroll
    for (int m = 1; m < 16; m <<= 1) {
        #pragma unroll
        for (int j = 0; j < 8; j++) {
            s8[j] += __shfl_xor_sync(0xffffffffu, s8[j], m);
            q8[j] += __shfl_xor_sync(0xffffffffu, q8[j], m);
        }
    }
    if (eg == 0) {
        #pragma unroll
        for (int j = 0; j < 8; j++) {
            atomicAdd(&d_s1[cg*8 + j], s8[j]);
            atomicAdd(&d_q1[cg*8 + j], q8[j]);
        }
    }
}

__global__ void k_fin1(const float* __restrict__ g1, const float* __restrict__ b1) {
    int c = threadIdx.x;
    float inv_n = 1.0f / (float)EDGES;
    float mu  = d_s1[c] * inv_n;
    float var = d_q1[c] * inv_n - mu*mu;
    float sc  = rsqrtf(var + BNEPS) * g1[c];
    d_scale1[c] = sc;
    d_shift1[c] = b1[c] - mu * sc;
}

// ---------------- gate + sum (fp16 input, uint4 loads), BN2 stats ----------------
// block = 32 atoms x 8 threads; thread covers 8 cols
__global__ __launch_bounds__(256) void k_gate_sum() {
    __shared__ float s2_sh[AF], q2_sh[AF];
    int tid = threadIdx.x;
    if (tid < AF) { s2_sh[tid] = 0.f; q2_sh[tid] = 0.f; }
    __syncthreads();

    int al = tid >> 3;
    int c0 = (tid & 7) * 8;
    int a  = blockIdx.x*32 + al;

    float scf[8], shf[8], scs[8], shs[8];
    *(float4*)&scf[0] = *(const float4*)&d_scale1[c0];
    *(float4*)&scf[4] = *(const float4*)&d_scale1[c0+4];
    *(float4*)&shf[0] = *(const float4*)&d_shift1[c0];
    *(float4*)&shf[4] = *(const float4*)&d_shift1[c0+4];
    *(float4*)&scs[0] = *(const float4*)&d_scale1[AF+c0];
    *(float4*)&scs[4] = *(const float4*)&d_scale1[AF+c0+4];
    *(float4*)&shs[0] = *(const float4*)&d_shift1[AF+c0];
    *(float4*)&shs[4] = *(const float4*)&d_shift1[AF+c0+4];

    float accv[8];
    #pragma unroll
    for (int j = 0; j < 8; j++) accv[j] = 0.f;

    size_t base = (size_t)a * MNBR * TWOAF;
    #pragma unroll
    for (int m = 0; m < MNBR; m++) {
        uint4 fv = *reinterpret_cast<const uint4*>(&d_gh[base + m*TWOAF + c0]);
        uint4 sv = *reinterpret_cast<const uint4*>(&d_gh[base + m*TWOAF + AF + c0]);
        const __half2* fh = (const __half2*)&fv;
        const __half2* sh = (const __half2*)&sv;
        #pragma unroll
        for (int p = 0; p < 4; p++) {
            float2 f = __half22float2(fh[p]);
            float2 s = __half22float2(sh[p]);
            float fx = f.x*scf[2*p]   + shf[2*p];
            float fy = f.y*scf[2*p+1] + shf[2*p+1];
            float sx = s.x*scs[2*p]   + shs[2*p];
            float sy = s.y*scs[2*p+1] + shs[2*p+1];
            accv[2*p]   += sigmoidf(fx) * softplusf(sx);
            accv[2*p+1] += sigmoidf(fy) * softplusf(sy);
        }
    }
    *(float4*)&d_summed[a*AF + c0]     = *(float4*)&accv[0];
    *(float4*)&d_summed[a*AF + c0 + 4] = *(float4*)&accv[4];
    #pragma unroll
    for (int j = 0; j < 8; j++) {
        atomicAdd(&s2_sh[c0 + j], accv[j]);
        atomicAdd(&q2_sh[c0 + j], accv[j]*accv[j]);
    }
    __syncthreads();
    if (tid < AF) {
        atomicAdd(&d_s2[tid], s2_sh[tid]);
        atomicAdd(&d_q2[tid], q2_sh[tid]);
    }
}

__global__ void k_fin2(const float* __restrict__ g2, const float* __restrict__ b2) {
    int c = threadIdx.x;
    float inv_n = 1.0f / (float)NATOMS;
    float mu  = d_s2[c] * inv_n;
    float var = d_q2[c] * inv_n - mu*mu;
    float sc  = rsqrtf(var + BNEPS) * g2[c];
    d_scale2[c] = sc;
    d_shift2[c] = b2[c] - mu * sc;
}

__global__ __launch_bounds__(256) void k_update_x() {
    int i = blockIdx.x*256 + threadIdx.x;
    int c = i & (AF-1);
    float v = d_summed[i] * d_scale2[c] + d_shift2[c];
    d_x[i] = softplusf(d_x[i] + v);
}

// ---------------- pool + head MLP ----------------
__global__ __launch_bounds__(128) void k_head(
    const float* __restrict__ fc1W, const float* __restrict__ fc1b,
    const float* __restrict__ fc2W, const float* __restrict__ fc2b,
    const float* __restrict__ outW, const float* __restrict__ outb,
    float* __restrict__ out)
{
    __shared__ float p[AF];
    __shared__ float h1[HF];
    __shared__ float red[HF];
    int tid = threadIdx.x;
    int b = blockIdx.x;

    if (tid < AF) {
        const float* xb = &d_x[(size_t)b * ATOMS_PER * AF];
        float s = 0.f;
        #pragma unroll
        for (int a = 0; a < ATOMS_PER; a++) s += xb[a*AF + tid];
        p[tid] = softplusf(s * (1.0f/ATOMS_PER));
    }
    __syncthreads();

    float acc = fc1b[tid];
    #pragma unroll 4
    for (int k = 0; k < AF; k++) acc += p[k] * fc1W[k*HF + tid];
    h1[tid] = softplusf(acc);
    __syncthreads();

    float acc2 = fc2b[tid];
    #pragma unroll 4
    for (int k = 0; k < HF; k++) acc2 += h1[k] * fc2W[k*HF + tid];
    float h2 = softplusf(acc2);

    red[tid] = h2 * outW[tid];
    __syncthreads();
    for (int s = HF/2; s > 0; s >>= 1) {
        if (tid < s) red[tid] += red[tid + s];
        __syncthreads();
    }
    if (tid == 0) out[b] = red[0] + outb[0];
}

// ---------------- launch ----------------
extern "C" void kernel_launch(void* const* d_in, const int* in_sizes, int n_in,
                              void* d_out, int out_size)
{
    const float* atom_fea = (const float*)d_in[0];
    const float* nbr_fea  = (const float*)d_in[1];
    const int*   nbr_idx  = (const int*)  d_in[2];
    const float* embW  = (const float*)d_in[4];
    const float* embB  = (const float*)d_in[5];
    const float* convW = (const float*)d_in[6];
    const float* convB = (const float*)d_in[7];
    const float* bn1g  = (const float*)d_in[8];
    const float* bn1b  = (const float*)d_in[9];
    const float* bn2g  = (const float*)d_in[10];
    const float* bn2b  = (const float*)d_in[11];
    const float* fc1W  = (const float*)d_in[12];
    const float* fc1b  = (const float*)d_in[13];
    const float* fc2W  = (const float*)d_in[14];
    const float* fc2b  = (const float*)d_in[15];
    const float* outW  = (const float*)d_in[16];
    const float* outb  = (const float*)d_in[17];
    float* out = (float*)d_out;

    k_embed<<<NATOMS/4, 256>>>(atom_fea, embW, embB);
    k_cvt_nbr<<<(EDGES/16)*3*32/256, 256>>>(nbr_fea);   // once: layer-invariant

    for (int l = 0; l < NCONV; l++) {
        const float* Wl = convW + (size_t)l*KTOT*TWOAF;
        k_cvt_x<<<(NATOMS/16)*4*32/256, 256>>>();
        k_zero_stats<<<1, 256>>>();
        k_cvt_Wp<<<16, 256>>>(Wl);
        k_cvt_W<<<KPAD*TWOAF/256, 256>>>(Wl + (size_t)TWOAF*TWOAF);
        k_atom_mma<<<NATOMS/16, 256>>>(convB + l*TWOAF);
        k_edge_mma<<<296, 256>>>(nbr_idx);
        k_fin1<<<1, 128>>>(bn1g + l*TWOAF, bn1b + l*TWOAF);
        k_gate_sum<<<NATOMS/32, 256>>>();
        k_fin2<<<1, 64>>>(bn2g + l*AF, bn2b + l*AF);
        k_update_x<<<NATOMS*AF/256, 256>>>();
    }

    k_head<<<NCRYS, 128>>>(fc1W, fc1b, fc2W, fc2b, outW, outb, out);
}